// round 2
// baseline (speedup 1.0000x reference)
#include <cuda_runtime.h>

#define BB 2
#define SS 2048
#define DD 1024
#define HH 16
#define DKH 64
#define BHH (BB*HH)

typedef unsigned long long u64t;

// ---- packed f32x2 helpers (FFMA2: 2 fp32 FLOPs per fma-pipe slot) ----------
__device__ __forceinline__ u64t dup2(float x) {
    u64t r; asm("mov.b64 %0,{%1,%1};" : "=l"(r) : "f"(x)); return r;
}
__device__ __forceinline__ u64t pack2(float a, float b) {
    u64t r; asm("mov.b64 %0,{%1,%2};" : "=l"(r) : "f"(a), "f"(b)); return r;
}
__device__ __forceinline__ void unpk2(u64t v, float& a, float& b) {
    asm("mov.b64 {%0,%1},%2;" : "=f"(a), "=f"(b) : "l"(v));
}
__device__ __forceinline__ void ffma2(u64t& d, u64t a, u64t b) {
    asm("fma.rn.f32x2 %0,%1,%2,%0;" : "+l"(d) : "l"(a), "l"(b));
}
__device__ __forceinline__ void fmul2(u64t& d, u64t a) {
    asm("mul.rn.f32x2 %0,%0,%1;" : "+l"(d) : "l"(a));
}

// Scratch (allocation-free rule: __device__ globals)
__device__ float g_q[BHH * SS * DKH];
__device__ float g_k[BHH * SS * DKH];
__device__ float g_v[BHH * SS * DKH];
__device__ float g_ctx[BB * SS * HH * DKH];

// ---------------------------------------------------------------------------
// Kernel 1: QKV projection. grid (32 token-tiles, 16 heads, 3); block 256.
// Tile: 128 tokens x 64 (full head), BK=32, Xs stored k-major, FFMA2 micro.
// ---------------------------------------------------------------------------
__global__ __launch_bounds__(256) void qkv_kernel(
    const float* __restrict__ X,
    const float* __restrict__ Wq, const float* __restrict__ bq,
    const float* __restrict__ Wk, const float* __restrict__ bk,
    const float* __restrict__ Wv, const float* __restrict__ bv)
{
    const int m0 = blockIdx.x * 128;
    const int h  = blockIdx.y;
    const int which = blockIdx.z;

    const float* W; const float* bias; float* out;
    if (which == 0)      { W = Wq; bias = bq; out = g_q; }
    else if (which == 1) { W = Wk; bias = bk; out = g_k; }
    else                 { W = Wv; bias = bv; out = g_v; }
    W    += (size_t)h * DD * DKH;
    bias += h * DKH;

    __shared__ float Xs[32][128];   // k-major
    __shared__ float Ws[32][64];    // k-major (natural)

    const int tid = threadIdx.x;
    const int ty = tid >> 4;       // 0..15 -> 8 rows each
    const int tx = tid & 15;       // 0..15 -> 4 cols each

    u64t acc[8][2] = {};           // 8 rows x 4 cols as 2 f32x2 pairs

    for (int k0 = 0; k0 < DD; k0 += 32) {
        // X tile 128x32: 1024 float4, 4 per thread, transposed into Xs
        #pragma unroll
        for (int l = 0; l < 4; l++) {
            int idx = tid + l * 256;
            int r = idx >> 3, c4 = idx & 7;
            float4 v = *(const float4*)&X[(size_t)(m0 + r) * DD + k0 + c4 * 4];
            Xs[c4 * 4 + 0][r] = v.x;
            Xs[c4 * 4 + 1][r] = v.y;
            Xs[c4 * 4 + 2][r] = v.z;
            Xs[c4 * 4 + 3][r] = v.w;
        }
        // W tile 32x64: 512 float4, 2 per thread
        #pragma unroll
        for (int l = 0; l < 2; l++) {
            int idx = tid + l * 256;
            int r = idx >> 4, c = idx & 15;
            *(float4*)&Ws[r][c * 4] = *(const float4*)&W[(size_t)(k0 + r) * DKH + c * 4];
        }
        __syncthreads();

        #pragma unroll 8
        for (int kk = 0; kk < 32; kk++) {
            float4 a0 = *(float4*)&Xs[kk][ty * 8];
            float4 a1 = *(float4*)&Xs[kk][ty * 8 + 4];
            float4 bv4 = *(float4*)&Ws[kk][tx * 4];
            u64t b0 = pack2(bv4.x, bv4.y);
            u64t b1 = pack2(bv4.z, bv4.w);
            float av[8] = {a0.x, a0.y, a0.z, a0.w, a1.x, a1.y, a1.z, a1.w};
            #pragma unroll
            for (int i = 0; i < 8; i++) {
                u64t ad = dup2(av[i]);
                ffma2(acc[i][0], ad, b0);
                ffma2(acc[i][1], ad, b1);
            }
        }
        __syncthreads();
    }

    const float4 bb = *(const float4*)&bias[tx * 4];
    #pragma unroll
    for (int i = 0; i < 8; i++) {
        int t  = m0 + ty * 8 + i;
        int b_ = t >> 11;
        int s_ = t & (SS - 1);
        float4 o;
        unpk2(acc[i][0], o.x, o.y);
        unpk2(acc[i][1], o.z, o.w);
        o.x += bb.x; o.y += bb.y; o.z += bb.z; o.w += bb.w;
        *(float4*)&out[((size_t)(b_ * HH + h) * SS + s_) * DKH + tx * 4] = o;
    }
}

// ---------------------------------------------------------------------------
// Kernel 2: flash attention per (bh, 128-query tile). grid (16, 32); block 256.
// ---------------------------------------------------------------------------
#define ATTN_SMEM_FLOATS (2 * 64 * 136 + 128 * 64 + 128 * 128)
#define ATTN_SMEM_BYTES  (ATTN_SMEM_FLOATS * 4)

__global__ __launch_bounds__(256) void attn_kernel()
{
    extern __shared__ float smem[];
    float (*Qst)[136] = (float(*)[136])(smem);
    float (*Kst)[136] = (float(*)[136])(smem + 64 * 136);
    float (*Vs)[64]   = (float(*)[64]) (smem + 2 * 64 * 136);
    float (*Ps)[128]  = (float(*)[128])(smem + 2 * 64 * 136 + 128 * 64);

    const int bh = blockIdx.y;
    const int q0 = blockIdx.x * 128;
    const float* Q = g_q + (size_t)bh * SS * DKH;
    const float* K = g_k + (size_t)bh * SS * DKH;
    const float* V = g_v + (size_t)bh * SS * DKH;

    const int tid = threadIdx.x;
    const int ty = tid >> 4;
    const int tx = tid & 15;

    // Load + transpose Q tile, pre-scaled by 1/sqrt(64)
    {
        int row  = tid >> 1;
        int half = tid & 1;
        #pragma unroll
        for (int it = 0; it < 8; it++) {
            int c = half * 8 + it;
            float4 v = *(const float4*)&Q[(size_t)(q0 + row) * DKH + c * 4];
            Qst[c * 4 + 0][row] = v.x * 0.125f;
            Qst[c * 4 + 1][row] = v.y * 0.125f;
            Qst[c * 4 + 2][row] = v.z * 0.125f;
            Qst[c * 4 + 3][row] = v.w * 0.125f;
        }
    }

    float m[8], l[8];
    u64t o2[8][2];
    #pragma unroll
    for (int i = 0; i < 8; i++) {
        m[i] = -1e30f; l[i] = 0.0f;
        o2[i][0] = 0; o2[i][1] = 0;
    }

    for (int t = 0; t < SS / 128; t++) {
        __syncthreads();   // previous tile fully consumed

        // load K tile transposed
        {
            int row = tid >> 1, half = tid & 1;
            #pragma unroll
            for (int it = 0; it < 8; it++) {
                int c = half * 8 + it;
                float4 v = *(const float4*)&K[(size_t)(t * 128 + row) * DKH + c * 4];
                Kst[c * 4 + 0][row] = v.x;
                Kst[c * 4 + 1][row] = v.y;
                Kst[c * 4 + 2][row] = v.z;
                Kst[c * 4 + 3][row] = v.w;
            }
        }
        // load V tile row-major
        #pragma unroll
        for (int lq = 0; lq < 8; lq++) {
            int idx = tid + lq * 256;
            int r = idx >> 4, c = idx & 15;
            *(float4*)&Vs[r][c * 4] =
                *(const float4*)&V[(size_t)(t * 128 + r) * DKH + c * 4];
        }
        __syncthreads();

        // S = Q K^T  (128x128 tile, 8x8 per thread, FFMA2 pairs along keys)
        u64t s2[8][4] = {};
        #pragma unroll 4
        for (int d = 0; d < 64; d++) {
            float4 a0 = *(float4*)&Qst[d][ty * 8];
            float4 a1 = *(float4*)&Qst[d][ty * 8 + 4];
            float4 b0 = *(float4*)&Kst[d][tx * 8];
            float4 b1 = *(float4*)&Kst[d][tx * 8 + 4];
            u64t bp0 = pack2(b0.x, b0.y);
            u64t bp1 = pack2(b0.z, b0.w);
            u64t bp2 = pack2(b1.x, b1.y);
            u64t bp3 = pack2(b1.z, b1.w);
            float av[8] = {a0.x, a0.y, a0.z, a0.w, a1.x, a1.y, a1.z, a1.w};
            #pragma unroll
            for (int i = 0; i < 8; i++) {
                u64t ad = dup2(av[i]);
                ffma2(s2[i][0], ad, bp0);
                ffma2(s2[i][1], ad, bp1);
                ffma2(s2[i][2], ad, bp2);
                ffma2(s2[i][3], ad, bp3);
            }
        }

        // online softmax per row (unpack lazily, row at a time) + stage P
        #pragma unroll
        for (int i = 0; i < 8; i++) {
            float s[8];
            unpk2(s2[i][0], s[0], s[1]);
            unpk2(s2[i][1], s[2], s[3]);
            unpk2(s2[i][2], s[4], s[5]);
            unpk2(s2[i][3], s[6], s[7]);
            float tm = s[0];
            #pragma unroll
            for (int j = 1; j < 8; j++) tm = fmaxf(tm, s[j]);
            #pragma unroll
            for (int msk = 1; msk < 16; msk <<= 1)
                tm = fmaxf(tm, __shfl_xor_sync(0xffffffffu, tm, msk));
            float mn = fmaxf(m[i], tm);
            float f  = __expf(m[i] - mn);
            m[i] = mn;
            float rs = 0.0f;
            #pragma unroll
            for (int j = 0; j < 8; j++) {
                s[j] = __expf(s[j] - mn);
                rs += s[j];
            }
            #pragma unroll
            for (int msk = 1; msk < 16; msk <<= 1)
                rs += __shfl_xor_sync(0xffffffffu, rs, msk);
            l[i] = l[i] * f + rs;
            u64t fd = dup2(f);
            fmul2(o2[i][0], fd);
            fmul2(o2[i][1], fd);
            *(float4*)&Ps[ty * 8 + i][tx * 8]     = make_float4(s[0], s[1], s[2], s[3]);
            *(float4*)&Ps[ty * 8 + i][tx * 8 + 4] = make_float4(s[4], s[5], s[6], s[7]);
        }
        __syncthreads();

        // O += P V  (128x64, 8x4 per thread, FFMA2 pairs along v-dim)
        #pragma unroll 2
        for (int key = 0; key < 128; key++) {
            float4 b = *(float4*)&Vs[key][tx * 4];
            u64t b0 = pack2(b.x, b.y);
            u64t b1 = pack2(b.z, b.w);
            #pragma unroll
            for (int i = 0; i < 8; i++) {
                u64t a = dup2(Ps[ty * 8 + i][key]);
                ffma2(o2[i][0], a, b0);
                ffma2(o2[i][1], a, b1);
            }
        }
    }

    // epilogue: normalize and write ctx in [B][S][H][DV] layout
    const int b_ = bh / HH;
    const int h_ = bh % HH;
    #pragma unroll
    for (int i = 0; i < 8; i++) {
        float inv = 1.0f / l[i];
        int srow = q0 + ty * 8 + i;
        float4 ov;
        unpk2(o2[i][0], ov.x, ov.y);
        unpk2(o2[i][1], ov.z, ov.w);
        ov.x *= inv; ov.y *= inv; ov.z *= inv; ov.w *= inv;
        *(float4*)&g_ctx[((size_t)(b_ * SS + srow) * HH + h_) * DKH + tx * 4] = ov;
    }
}

// ---------------------------------------------------------------------------
// Kernel 3: output projection. grid (32, 8); block 256; 128x128, BK=32, FFMA2.
// ---------------------------------------------------------------------------
__global__ __launch_bounds__(256) void out_kernel(
    const float* __restrict__ Wo, const float* __restrict__ bo,
    float* __restrict__ out)
{
    __shared__ float As[32][128];   // k-major
    __shared__ float Bs[32][128];   // k-major (natural)

    const int m0 = blockIdx.x * 128;
    const int n0 = blockIdx.y * 128;
    const int tid = threadIdx.x;
    const int ty = tid >> 4;
    const int tx = tid & 15;

    u64t acc[8][4] = {};

    for (int k0 = 0; k0 < HH * DKH; k0 += 32) {
        // A tile 128x32 transposed: 1024 float4, 4 per thread
        #pragma unroll
        for (int l = 0; l < 4; l++) {
            int idx = tid + l * 256;
            int r = idx >> 3, c4 = idx & 7;
            float4 v = *(const float4*)&g_ctx[(size_t)(m0 + r) * DD + k0 + c4 * 4];
            As[c4 * 4 + 0][r] = v.x;
            As[c4 * 4 + 1][r] = v.y;
            As[c4 * 4 + 2][r] = v.z;
            As[c4 * 4 + 3][r] = v.w;
        }
        // B tile 32x128: 1024 float4, 4 per thread
        #pragma unroll
        for (int l = 0; l < 4; l++) {
            int idx = tid + l * 256;
            int r = idx >> 5, c = idx & 31;
            *(float4*)&Bs[r][c * 4] = *(const float4*)&Wo[(size_t)(k0 + r) * DD + n0 + c * 4];
        }
        __syncthreads();

        #pragma unroll 8
        for (int kk = 0; kk < 32; kk++) {
            float4 a0 = *(float4*)&As[kk][ty * 8];
            float4 a1 = *(float4*)&As[kk][ty * 8 + 4];
            float4 b0 = *(float4*)&Bs[kk][tx * 8];
            float4 b1 = *(float4*)&Bs[kk][tx * 8 + 4];
            u64t bp0 = pack2(b0.x, b0.y);
            u64t bp1 = pack2(b0.z, b0.w);
            u64t bp2 = pack2(b1.x, b1.y);
            u64t bp3 = pack2(b1.z, b1.w);
            float av[8] = {a0.x, a0.y, a0.z, a0.w, a1.x, a1.y, a1.z, a1.w};
            #pragma unroll
            for (int i = 0; i < 8; i++) {
                u64t ad = dup2(av[i]);
                ffma2(acc[i][0], ad, bp0);
                ffma2(acc[i][1], ad, bp1);
                ffma2(acc[i][2], ad, bp2);
                ffma2(acc[i][3], ad, bp3);
            }
        }
        __syncthreads();
    }

    float4 bb0 = *(const float4*)&bo[n0 + tx * 8];
    float4 bb1 = *(const float4*)&bo[n0 + tx * 8 + 4];
    #pragma unroll
    for (int i = 0; i < 8; i++) {
        int r = m0 + ty * 8 + i;
        float4 o0, o1;
        unpk2(acc[i][0], o0.x, o0.y);
        unpk2(acc[i][1], o0.z, o0.w);
        unpk2(acc[i][2], o1.x, o1.y);
        unpk2(acc[i][3], o1.z, o1.w);
        o0.x += bb0.x; o0.y += bb0.y; o0.z += bb0.z; o0.w += bb0.w;
        o1.x += bb1.x; o1.y += bb1.y; o1.z += bb1.z; o1.w += bb1.w;
        *(float4*)&out[(size_t)r * DD + n0 + tx * 8]     = o0;
        *(float4*)&out[(size_t)r * DD + n0 + tx * 8 + 4] = o1;
    }
}

// ---------------------------------------------------------------------------
extern "C" void kernel_launch(void* const* d_in, const int* in_sizes, int n_in,
                              void* d_out, int out_size)
{
    const float* X  = (const float*)d_in[0];
    const float* Wq = (const float*)d_in[1];
    const float* bq = (const float*)d_in[2];
    const float* Wk = (const float*)d_in[3];
    const float* bk = (const float*)d_in[4];
    const float* Wv = (const float*)d_in[5];
    const float* bv = (const float*)d_in[6];
    const float* Wo = (const float*)d_in[7];
    const float* bo = (const float*)d_in[8];
    float* out = (float*)d_out;

    cudaFuncSetAttribute(attn_kernel,
                         cudaFuncAttributeMaxDynamicSharedMemorySize,
                         ATTN_SMEM_BYTES);

    qkv_kernel<<<dim3(32, 16, 3), 256>>>(X, Wq, bq, Wk, bk, Wv, bv);
    attn_kernel<<<dim3(16, 32), 256, ATTN_SMEM_BYTES>>>();
    out_kernel<<<dim3(32, 8), 256>>>(Wo, bo, out);
}

// round 4
// speedup vs baseline: 1.2095x; 1.2095x over previous
#include <cuda_runtime.h>
#include <cuda_bf16.h>
#include <cstdint>

#define BB 2
#define SS 2048
#define DD 1024
#define HH 16
#define DKH 64
#define BHH (BB*HH)

// ---------------------------------------------------------------------------
// Scratch (allocation-free rule: __device__ globals)
// ---------------------------------------------------------------------------
__device__ float g_q[BHH * SS * DKH];
__device__ float g_k[BHH * SS * DKH];
__device__ float g_v[BHH * SS * DKH];
__device__ float g_ctx[BB * SS * HH * DKH];

// bf16 hi/lo split copies
__device__ __nv_bfloat16 g_xhi[BB * SS * DD];
__device__ __nv_bfloat16 g_xlo[BB * SS * DD];
// W transposed: [(proj*16+h)*64 + n][k]  (k contiguous)
__device__ __nv_bfloat16 g_whi[3 * HH * DKH * DD];
__device__ __nv_bfloat16 g_wlo[3 * HH * DKH * DD];

// ---------------------------------------------------------------------------
// HMMA helpers (family-portable: compile for plain sm_103)
// ---------------------------------------------------------------------------
__device__ __forceinline__ uint32_t smem_to_u32(const void* p) {
    uint32_t a;
    asm("{ .reg .u64 t; cvta.to.shared.u64 t, %1; cvt.u32.u64 %0, t; }"
        : "=r"(a) : "l"(p));
    return a;
}
__device__ __forceinline__ void ldsm_x4(uint32_t addr, uint32_t* r) {
    asm volatile("ldmatrix.sync.aligned.m8n8.x4.shared.b16 {%0,%1,%2,%3}, [%4];"
        : "=r"(r[0]), "=r"(r[1]), "=r"(r[2]), "=r"(r[3]) : "r"(addr));
}
__device__ __forceinline__ void mma_bf16(float* d, const uint32_t* a,
                                         uint32_t b0, uint32_t b1) {
    asm volatile(
        "mma.sync.aligned.m16n8k16.row.col.f32.bf16.bf16.f32 "
        "{%0,%1,%2,%3}, {%4,%5,%6,%7}, {%8,%9}, {%0,%1,%2,%3};"
        : "+f"(d[0]), "+f"(d[1]), "+f"(d[2]), "+f"(d[3])
        : "r"(a[0]), "r"(a[1]), "r"(a[2]), "r"(a[3]), "r"(b0), "r"(b1));
}

// ---------------------------------------------------------------------------
// Prep kernel A: split X into bf16 hi/lo.
// ---------------------------------------------------------------------------
__global__ __launch_bounds__(256) void conv_x_kernel(const float4* __restrict__ X4)
{
    int i0 = blockIdx.x * 256 + threadIdx.x;
    #pragma unroll
    for (int l = 0; l < 2; l++) {
        int i = i0 + l * 524288;                       // total 1,048,576 float4
        float4 v = X4[i];
        float vv[4] = {v.x, v.y, v.z, v.w};
        union { float2 f; __nv_bfloat16 h[4]; } hi, lo;
        #pragma unroll
        for (int j = 0; j < 4; j++) {
            hi.h[j] = __float2bfloat16(vv[j]);
            lo.h[j] = __float2bfloat16(vv[j] - __bfloat162float(hi.h[j]));
        }
        ((float2*)g_xhi)[i] = hi.f;
        ((float2*)g_xlo)[i] = lo.f;
    }
}

// ---------------------------------------------------------------------------
// Prep kernel B: transpose + split W.  W[h][k][n] -> Wt[(proj*16+h)*64+n][k]
// ---------------------------------------------------------------------------
__global__ __launch_bounds__(256) void conv_w_kernel(
    const float* __restrict__ Wq, const float* __restrict__ Wk,
    const float* __restrict__ Wv)
{
    __shared__ float ts[64][65];
    const int k0   = blockIdx.x * 64;
    const int h    = blockIdx.y;
    const int proj = blockIdx.z;
    const float* W = (proj == 0) ? Wq : (proj == 1) ? Wk : Wv;
    W += (size_t)h * DD * DKH;

    const int tid = threadIdx.x;
    #pragma unroll
    for (int l = 0; l < 4; l++) {
        int idx = tid + l * 256;
        int r = idx >> 4, c4 = idx & 15;
        float4 v = *(const float4*)&W[(size_t)(k0 + r) * DKH + c4 * 4];
        ts[r][c4 * 4 + 0] = v.x;
        ts[r][c4 * 4 + 1] = v.y;
        ts[r][c4 * 4 + 2] = v.z;
        ts[r][c4 * 4 + 3] = v.w;
    }
    __syncthreads();
    #pragma unroll
    for (int l = 0; l < 4; l++) {
        int idx = tid + l * 256;
        int nr = idx >> 4, kc = idx & 15;
        size_t orow = ((size_t)(proj * HH + h) * DKH + nr) * DD + k0 + kc * 4;
        #pragma unroll
        for (int j = 0; j < 4; j++) {
            float v = ts[kc * 4 + j][nr];
            __nv_bfloat16 hi = __float2bfloat16(v);
            __nv_bfloat16 lo = __float2bfloat16(v - __bfloat162float(hi));
            g_whi[orow + j] = hi;
            g_wlo[orow + j] = lo;
        }
    }
}

// ---------------------------------------------------------------------------
// QKV GEMM on HMMA (mma.sync bf16, hi/lo split, fp32 accum).
// grid (32 token tiles, 8 head-pairs, 3 proj); block 256 = 8 warps (4M x 2N).
// CTA tile M=128, N=128, K chunked at 64.
// ---------------------------------------------------------------------------
#define QPAD 8                         // pad bf16 per row -> stride 144B
#define QROW (64 + QPAD)               // bf16 per smem row
#define QTILE_BYTES (128 * QROW * 2)   // 18432
#define QKV_SM_AHI 0
#define QKV_SM_ALO (QTILE_BYTES)
#define QKV_SM_BHI (2 * QTILE_BYTES)
#define QKV_SM_BLO (3 * QTILE_BYTES)
#define QKV_SMEM_BYTES (4 * QTILE_BYTES)

__device__ __forceinline__ void load_tile_q(
    char* smem, int dst_off, const __nv_bfloat16* __restrict__ src,
    int k0, int tid)
{
    #pragma unroll
    for (int l = 0; l < 4; l++) {
        int idx = tid + l * 256;
        int r = idx >> 3, c = idx & 7;            // row 0..127, 16B chunk 0..7
        float4 v = *(const float4*)((const char*)src + ((size_t)r * DD + k0) * 2 + c * 16);
        *(float4*)(smem + dst_off + r * (QROW * 2) + c * 16) = v;
    }
}

__global__ __launch_bounds__(256, 1) void qkv_mma_kernel(
    const float* __restrict__ bq, const float* __restrict__ bk,
    const float* __restrict__ bv)
{
    extern __shared__ char smem[];
    const uint32_t smem_base = smem_to_u32(smem);
    const int tid  = threadIdx.x;
    const int wid  = tid >> 5;
    const int lane = tid & 31;
    const int warpM = wid & 3;          // 4 M-groups of 32 rows
    const int warpN = wid >> 2;         // 2 N-groups of 64 cols

    const int m0   = blockIdx.x * 128;
    const int hg   = blockIdx.y;        // head pair 0..7
    const int proj = blockIdx.z;

    const float* bias = (proj == 0) ? bq : (proj == 1) ? bk : bv;
    float* out = (proj == 0) ? g_q : (proj == 1) ? g_k : g_v;

    const __nv_bfloat16* Ahi = g_xhi + (size_t)m0 * DD;
    const __nv_bfloat16* Alo = g_xlo + (size_t)m0 * DD;
    const size_t brow = ((size_t)proj * HH * DKH + (size_t)hg * 128) * DD;
    const __nv_bfloat16* Bhi = g_whi + brow;
    const __nv_bfloat16* Blo = g_wlo + brow;

    float acc[2][8][4];
    #pragma unroll
    for (int i = 0; i < 2; i++)
        #pragma unroll
        for (int j = 0; j < 8; j++)
            #pragma unroll
            for (int d = 0; d < 4; d++) acc[i][j][d] = 0.0f;

    // ldmatrix base addresses (row = lane%16, 16B chunk = lane/16)
    const int lrow  = lane & 15;
    const int lhalf = lane >> 4;
    const uint32_t a_base = smem_base +
        (uint32_t)((warpM * 32 + lrow) * (QROW * 2) + lhalf * 16);
    const uint32_t b_base = smem_base +
        (uint32_t)((warpN * 64 + lrow) * (QROW * 2) + lhalf * 16);

    for (int ch = 0; ch < 16; ch++) {
        const int k0 = ch * 64;
        if (ch) __syncthreads();        // previous chunk consumed
        load_tile_q(smem, QKV_SM_AHI, Ahi, k0, tid);
        load_tile_q(smem, QKV_SM_ALO, Alo, k0, tid);
        load_tile_q(smem, QKV_SM_BHI, Bhi, k0, tid);
        load_tile_q(smem, QKV_SM_BLO, Blo, k0, tid);
        __syncthreads();

        #pragma unroll
        for (int ks = 0; ks < 4; ks++) {
            const uint32_t koff = ks * 32;   // 16 bf16 = 32B
            uint32_t ahi[2][4], alo[2][4];
            #pragma unroll
            for (int am = 0; am < 2; am++) {
                ldsm_x4(a_base + QKV_SM_AHI + am * 16 * (QROW * 2) + koff, ahi[am]);
                ldsm_x4(a_base + QKV_SM_ALO + am * 16 * (QROW * 2) + koff, alo[am]);
            }
            uint32_t bhi[4][4], blo[4][4];
            #pragma unroll
            for (int bn = 0; bn < 4; bn++) {
                ldsm_x4(b_base + QKV_SM_BHI + bn * 16 * (QROW * 2) + koff, bhi[bn]);
                ldsm_x4(b_base + QKV_SM_BLO + bn * 16 * (QROW * 2) + koff, blo[bn]);
            }
            #pragma unroll
            for (int am = 0; am < 2; am++) {
                #pragma unroll
                for (int bn = 0; bn < 4; bn++) {
                    // n-atom 2*bn   : frags {r0, r2};  n-atom 2*bn+1 : {r1, r3}
                    mma_bf16(acc[am][2*bn],   ahi[am], bhi[bn][0], bhi[bn][2]);
                    mma_bf16(acc[am][2*bn+1], ahi[am], bhi[bn][1], bhi[bn][3]);
                    mma_bf16(acc[am][2*bn],   ahi[am], blo[bn][0], blo[bn][2]);
                    mma_bf16(acc[am][2*bn+1], ahi[am], blo[bn][1], blo[bn][3]);
                    mma_bf16(acc[am][2*bn],   alo[am], bhi[bn][0], bhi[bn][2]);
                    mma_bf16(acc[am][2*bn+1], alo[am], bhi[bn][1], bhi[bn][3]);
                }
            }
        }
    }

    // epilogue: write fp32 + bias to out[((b*HH+h)*SS+s)*64 + dk]
    #pragma unroll
    for (int am = 0; am < 2; am++) {
        #pragma unroll
        for (int rh = 0; rh < 2; rh++) {
            const int r_local = warpM * 32 + am * 16 + rh * 8 + (lane >> 2);
            const int token = m0 + r_local;
            const int b_ = token >> 11;
            const int s_ = token & (SS - 1);
            #pragma unroll
            for (int na = 0; na < 8; na++) {
                const int n_local = warpN * 64 + na * 8 + (lane & 3) * 2;
                const int ng = hg * 128 + n_local;
                const int h  = ng >> 6;
                const int dk = ng & 63;
                float2 o;
                o.x = acc[am][na][rh * 2 + 0] + __ldg(&bias[h * DKH + dk]);
                o.y = acc[am][na][rh * 2 + 1] + __ldg(&bias[h * DKH + dk + 1]);
                *(float2*)&out[(((size_t)(b_ * HH + h) * SS + s_) * DKH + dk)] = o;
            }
        }
    }
}

// ---------------------------------------------------------------------------
// Kernel 2: flash attention per (bh, 128-query tile) — R1 fp32 version.
// ---------------------------------------------------------------------------
#define ATTN_SMEM_FLOATS (2 * 64 * 136 + 128 * 64 + 128 * 128)
#define ATTN_SMEM_BYTES  (ATTN_SMEM_FLOATS * 4)

__global__ __launch_bounds__(256) void attn_kernel()
{
    extern __shared__ float smemf[];
    float (*Qst)[136] = (float(*)[136])(smemf);
    float (*Kst)[136] = (float(*)[136])(smemf + 64 * 136);
    float (*Vs)[64]   = (float(*)[64]) (smemf + 2 * 64 * 136);
    float (*Ps)[128]  = (float(*)[128])(smemf + 2 * 64 * 136 + 128 * 64);

    const int bh = blockIdx.y;
    const int q0 = blockIdx.x * 128;
    const float* Q = g_q + (size_t)bh * SS * DKH;
    const float* K = g_k + (size_t)bh * SS * DKH;
    const float* V = g_v + (size_t)bh * SS * DKH;

    const int tid = threadIdx.x;
    const int ty = tid >> 4;
    const int tx = tid & 15;

    {
        int row  = tid >> 1;
        int half = tid & 1;
        #pragma unroll
        for (int it = 0; it < 8; it++) {
            int c = half * 8 + it;
            float4 v = *(const float4*)&Q[(size_t)(q0 + row) * DKH + c * 4];
            Qst[c * 4 + 0][row] = v.x * 0.125f;
            Qst[c * 4 + 1][row] = v.y * 0.125f;
            Qst[c * 4 + 2][row] = v.z * 0.125f;
            Qst[c * 4 + 3][row] = v.w * 0.125f;
        }
    }

    float m[8], l[8], o[8][4];
    #pragma unroll
    for (int i = 0; i < 8; i++) {
        m[i] = -1e30f; l[i] = 0.0f;
        #pragma unroll
        for (int j = 0; j < 4; j++) o[i][j] = 0.0f;
    }

    for (int t = 0; t < SS / 128; t++) {
        __syncthreads();

        {
            int row = tid >> 1, half = tid & 1;
            #pragma unroll
            for (int it = 0; it < 8; it++) {
                int c = half * 8 + it;
                float4 v = *(const float4*)&K[(size_t)(t * 128 + row) * DKH + c * 4];
                Kst[c * 4 + 0][row] = v.x;
                Kst[c * 4 + 1][row] = v.y;
                Kst[c * 4 + 2][row] = v.z;
                Kst[c * 4 + 3][row] = v.w;
            }
        }
        #pragma unroll
        for (int lq = 0; lq < 8; lq++) {
            int idx = tid + lq * 256;
            int r = idx >> 4, c = idx & 15;
            *(float4*)&Vs[r][c * 4] =
                *(const float4*)&V[(size_t)(t * 128 + r) * DKH + c * 4];
        }
        __syncthreads();

        float s[8][8] = {};
        #pragma unroll 4
        for (int d = 0; d < 64; d++) {
            float4 a0 = *(float4*)&Qst[d][ty * 8];
            float4 a1 = *(float4*)&Qst[d][ty * 8 + 4];
            float4 b0 = *(float4*)&Kst[d][tx * 8];
            float4 b1 = *(float4*)&Kst[d][tx * 8 + 4];
            float a[8] = {a0.x, a0.y, a0.z, a0.w, a1.x, a1.y, a1.z, a1.w};
            float b[8] = {b0.x, b0.y, b0.z, b0.w, b1.x, b1.y, b1.z, b1.w};
            #pragma unroll
            for (int i = 0; i < 8; i++)
                #pragma unroll
                for (int j = 0; j < 8; j++)
                    s[i][j] = fmaf(a[i], b[j], s[i][j]);
        }

        #pragma unroll
        for (int i = 0; i < 8; i++) {
            float tm = s[i][0];
            #pragma unroll
            for (int j = 1; j < 8; j++) tm = fmaxf(tm, s[i][j]);
            #pragma unroll
            for (int msk = 1; msk < 16; msk <<= 1)
                tm = fmaxf(tm, __shfl_xor_sync(0xffffffffu, tm, msk));
            float mn = fmaxf(m[i], tm);
            float f  = __expf(m[i] - mn);
            m[i] = mn;
            float rs = 0.0f;
            #pragma unroll
            for (int j = 0; j < 8; j++) {
                s[i][j] = __expf(s[i][j] - mn);
                rs += s[i][j];
            }
            #pragma unroll
            for (int msk = 1; msk < 16; msk <<= 1)
                rs += __shfl_xor_sync(0xffffffffu, rs, msk);
            l[i] = l[i] * f + rs;
            #pragma unroll
            for (int j = 0; j < 4; j++) o[i][j] *= f;
        }

        #pragma unroll
        for (int i = 0; i < 8; i++) {
            *(float4*)&Ps[ty * 8 + i][tx * 8]     = make_float4(s[i][0], s[i][1], s[i][2], s[i][3]);
            *(float4*)&Ps[ty * 8 + i][tx * 8 + 4] = make_float4(s[i][4], s[i][5], s[i][6], s[i][7]);
        }
        __syncthreads();

        #pragma unroll 2
        for (int key = 0; key < 128; key++) {
            float4 b = *(float4*)&Vs[key][tx * 4];
            #pragma unroll
            for (int i = 0; i < 8; i++) {
                float a = Ps[ty * 8 + i][key];
                o[i][0] = fmaf(a, b.x, o[i][0]);
                o[i][1] = fmaf(a, b.y, o[i][1]);
                o[i][2] = fmaf(a, b.z, o[i][2]);
                o[i][3] = fmaf(a, b.w, o[i][3]);
            }
        }
    }

    const int b_ = bh / HH;
    const int h_ = bh % HH;
    #pragma unroll
    for (int i = 0; i < 8; i++) {
        float inv = 1.0f / l[i];
        int srow = q0 + ty * 8 + i;
        float4 ov = make_float4(o[i][0] * inv, o[i][1] * inv, o[i][2] * inv, o[i][3] * inv);
        *(float4*)&g_ctx[((size_t)(b_ * SS + srow) * HH + h_) * DKH + tx * 4] = ov;
    }
}

// ---------------------------------------------------------------------------
// Kernel 3: output projection — R1 fp32 version.
// ---------------------------------------------------------------------------
__global__ __launch_bounds__(256) void out_kernel(
    const float* __restrict__ Wo, const float* __restrict__ bo,
    float* __restrict__ out)
{
    __shared__ float As[128][16];
    __shared__ float Bs[16][128];

    const int m0 = blockIdx.x * 128;
    const int n0 = blockIdx.y * 128;
    const int tid = threadIdx.x;
    const int ty = tid >> 4;
    const int tx = tid & 15;

    float acc[8][8] = {};

    for (int k0 = 0; k0 < HH * DKH; k0 += 16) {
        #pragma unroll
        for (int l = 0; l < 2; l++) {
            int idx = tid + l * 256;
            int r = idx >> 2, c = idx & 3;
            *(float4*)&As[r][c * 4] =
                *(const float4*)&g_ctx[(size_t)(m0 + r) * DD + k0 + c * 4];
        }
        #pragma unroll
        for (int l = 0; l < 2; l++) {
            int idx = tid + l * 256;
            int r = idx >> 5, c = idx & 31;
            *(float4*)&Bs[r][c * 4] =
                *(const float4*)&Wo[(size_t)(k0 + r) * DD + n0 + c * 4];
        }
        __syncthreads();

        #pragma unroll
        for (int kk = 0; kk < 16; kk++) {
            float a[8];
            #pragma unroll
            for (int i = 0; i < 8; i++) a[i] = As[ty * 8 + i][kk];
            float4 b0 = *(float4*)&Bs[kk][tx * 8];
            float4 b1 = *(float4*)&Bs[kk][tx * 8 + 4];
            float b[8] = {b0.x, b0.y, b0.z, b0.w, b1.x, b1.y, b1.z, b1.w};
            #pragma unroll
            for (int i = 0; i < 8; i++)
                #pragma unroll
                for (int j = 0; j < 8; j++)
                    acc[i][j] = fmaf(a[i], b[j], acc[i][j]);
        }
        __syncthreads();
    }

    float4 bb0 = *(const float4*)&bo[n0 + tx * 8];
    float4 bb1 = *(const float4*)&bo[n0 + tx * 8 + 4];
    #pragma unroll
    for (int i = 0; i < 8; i++) {
        int r = m0 + ty * 8 + i;
        float4 o0 = make_float4(acc[i][0] + bb0.x, acc[i][1] + bb0.y,
                                acc[i][2] + bb0.z, acc[i][3] + bb0.w);
        float4 o1 = make_float4(acc[i][4] + bb1.x, acc[i][5] + bb1.y,
                                acc[i][6] + bb1.z, acc[i][7] + bb1.w);
        *(float4*)&out[(size_t)r * DD + n0 + tx * 8]     = o0;
        *(float4*)&out[(size_t)r * DD + n0 + tx * 8 + 4] = o1;
    }
}

// ---------------------------------------------------------------------------
extern "C" void kernel_launch(void* const* d_in, const int* in_sizes, int n_in,
                              void* d_out, int out_size)
{
    const float* X  = (const float*)d_in[0];
    const float* Wq = (const float*)d_in[1];
    const float* bq = (const float*)d_in[2];
    const float* Wk = (const float*)d_in[3];
    const float* bk = (const float*)d_in[4];
    const float* Wv = (const float*)d_in[5];
    const float* bv = (const float*)d_in[6];
    const float* Wo = (const float*)d_in[7];
    const float* bo = (const float*)d_in[8];
    float* out = (float*)d_out;

    cudaFuncSetAttribute(attn_kernel,
                         cudaFuncAttributeMaxDynamicSharedMemorySize,
                         ATTN_SMEM_BYTES);
    cudaFuncSetAttribute(qkv_mma_kernel,
                         cudaFuncAttributeMaxDynamicSharedMemorySize,
                         QKV_SMEM_BYTES);

    conv_x_kernel<<<2048, 256>>>((const float4*)X);
    conv_w_kernel<<<dim3(16, 16, 3), 256>>>(Wq, Wk, Wv);
    qkv_mma_kernel<<<dim3(32, 8, 3), 256, QKV_SMEM_BYTES>>>(bq, bk, bv);
    attn_kernel<<<dim3(16, 32), 256, ATTN_SMEM_BYTES>>>();
    out_kernel<<<dim3(32, 8), 256>>>(Wo, bo, out);
}

// round 5
// speedup vs baseline: 2.3017x; 1.9030x over previous
#include <cuda_runtime.h>
#include <cuda_bf16.h>
#include <cstdint>

#define BB 2
#define SS 2048
#define DD 1024
#define HH 16
#define DKH 64
#define BHH (BB*HH)

// ---------------------------------------------------------------------------
// Scratch (allocation-free rule: __device__ globals) — all bf16 hi/lo pairs
// ---------------------------------------------------------------------------
__device__ __nv_bfloat16 g_xhi[BB * SS * DD];
__device__ __nv_bfloat16 g_xlo[BB * SS * DD];
__device__ __nv_bfloat16 g_whi[3 * HH * DKH * DD];   // [(proj*16+h)*64+n][k]
__device__ __nv_bfloat16 g_wlo[3 * HH * DKH * DD];
__device__ __nv_bfloat16 g_qhi[BHH * SS * DKH];      // [bh][s][64] (x 1/8)
__device__ __nv_bfloat16 g_qlo[BHH * SS * DKH];
__device__ __nv_bfloat16 g_khi[BHH * SS * DKH];
__device__ __nv_bfloat16 g_klo[BHH * SS * DKH];
__device__ __nv_bfloat16 g_vhi[BHH * SS * DKH];
__device__ __nv_bfloat16 g_vlo[BHH * SS * DKH];
__device__ __nv_bfloat16 g_chi[BB * SS * HH * DKH];  // ctx [token][1024]
__device__ __nv_bfloat16 g_clo[BB * SS * HH * DKH];
__device__ __nv_bfloat16 g_wohi[DD * DD];            // Wo^T [n][k]
__device__ __nv_bfloat16 g_wolo[DD * DD];

// ---------------------------------------------------------------------------
// HMMA helpers
// ---------------------------------------------------------------------------
__device__ __forceinline__ uint32_t smem_to_u32(const void* p) {
    uint32_t a;
    asm("{ .reg .u64 t; cvta.to.shared.u64 t, %1; cvt.u32.u64 %0, t; }"
        : "=r"(a) : "l"(p));
    return a;
}
__device__ __forceinline__ void ldsm_x4(uint32_t addr, uint32_t* r) {
    asm volatile("ldmatrix.sync.aligned.m8n8.x4.shared.b16 {%0,%1,%2,%3}, [%4];"
        : "=r"(r[0]), "=r"(r[1]), "=r"(r[2]), "=r"(r[3]) : "r"(addr));
}
__device__ __forceinline__ void ldsm_x4_t(uint32_t addr, uint32_t* r) {
    asm volatile("ldmatrix.sync.aligned.m8n8.x4.trans.shared.b16 {%0,%1,%2,%3}, [%4];"
        : "=r"(r[0]), "=r"(r[1]), "=r"(r[2]), "=r"(r[3]) : "r"(addr));
}
__device__ __forceinline__ void mma_bf16(float* d, const uint32_t* a,
                                         uint32_t b0, uint32_t b1) {
    asm volatile(
        "mma.sync.aligned.m16n8k16.row.col.f32.bf16.bf16.f32 "
        "{%0,%1,%2,%3}, {%4,%5,%6,%7}, {%8,%9}, {%0,%1,%2,%3};"
        : "+f"(d[0]), "+f"(d[1]), "+f"(d[2]), "+f"(d[3])
        : "r"(a[0]), "r"(a[1]), "r"(a[2]), "r"(a[3]), "r"(b0), "r"(b1));
}
// pack two fp32 -> bf16x2 reg (lo = first arg)
__device__ __forceinline__ uint32_t pkbf(float lo, float hi) {
    uint32_t r;
    asm("cvt.rn.bf16x2.f32 %0, %1, %2;" : "=r"(r) : "f"(hi), "f"(lo));
    return r;
}
__device__ __forceinline__ void split2(float v, __nv_bfloat16& h, float& l) {
    h = __float2bfloat16(v);
    l = v - __bfloat162float(h);
}

// ---------------------------------------------------------------------------
// Prep A: split X into bf16 hi/lo.
// ---------------------------------------------------------------------------
__global__ __launch_bounds__(256) void conv_x_kernel(const float4* __restrict__ X4)
{
    int i0 = blockIdx.x * 256 + threadIdx.x;
    #pragma unroll
    for (int l = 0; l < 2; l++) {
        int i = i0 + l * 524288;
        float4 v = X4[i];
        float vv[4] = {v.x, v.y, v.z, v.w};
        union { float2 f; __nv_bfloat16 h[4]; } hi, lo;
        #pragma unroll
        for (int j = 0; j < 4; j++) {
            float lw; split2(vv[j], hi.h[j], lw);
            lo.h[j] = __float2bfloat16(lw);
        }
        ((float2*)g_xhi)[i] = hi.f;
        ((float2*)g_xlo)[i] = lo.f;
    }
}

// ---------------------------------------------------------------------------
// Prep B: transpose + split Wq/Wk/Wv.
// ---------------------------------------------------------------------------
__global__ __launch_bounds__(256) void conv_w_kernel(
    const float* __restrict__ Wq, const float* __restrict__ Wk,
    const float* __restrict__ Wv)
{
    __shared__ float ts[64][65];
    const int k0   = blockIdx.x * 64;
    const int h    = blockIdx.y;
    const int proj = blockIdx.z;
    const float* W = (proj == 0) ? Wq : (proj == 1) ? Wk : Wv;
    W += (size_t)h * DD * DKH;

    const int tid = threadIdx.x;
    #pragma unroll
    for (int l = 0; l < 4; l++) {
        int idx = tid + l * 256;
        int r = idx >> 4, c4 = idx & 15;
        float4 v = *(const float4*)&W[(size_t)(k0 + r) * DKH + c4 * 4];
        ts[r][c4 * 4 + 0] = v.x;
        ts[r][c4 * 4 + 1] = v.y;
        ts[r][c4 * 4 + 2] = v.z;
        ts[r][c4 * 4 + 3] = v.w;
    }
    __syncthreads();
    #pragma unroll
    for (int l = 0; l < 4; l++) {
        int idx = tid + l * 256;
        int nr = idx >> 4, kc = idx & 15;
        size_t orow = ((size_t)(proj * HH + h) * DKH + nr) * DD + k0 + kc * 4;
        #pragma unroll
        for (int j = 0; j < 4; j++) {
            float v = ts[kc * 4 + j][nr];
            __nv_bfloat16 hb; float lw; split2(v, hb, lw);
            g_whi[orow + j] = hb;
            g_wlo[orow + j] = __float2bfloat16(lw);
        }
    }
}

// ---------------------------------------------------------------------------
// Prep C: transpose + split Wo [k=1024][n=1024] -> [n][k].
// grid (16 k-tiles, 16 n-tiles), block 256
// ---------------------------------------------------------------------------
__global__ __launch_bounds__(256) void conv_wo_kernel(const float* __restrict__ Wo)
{
    __shared__ float ts[64][65];
    const int k0 = blockIdx.x * 64;
    const int n0 = blockIdx.y * 64;
    const int tid = threadIdx.x;
    #pragma unroll
    for (int l = 0; l < 4; l++) {
        int idx = tid + l * 256;
        int r = idx >> 4, c4 = idx & 15;
        float4 v = *(const float4*)&Wo[(size_t)(k0 + r) * DD + n0 + c4 * 4];
        ts[r][c4 * 4 + 0] = v.x;
        ts[r][c4 * 4 + 1] = v.y;
        ts[r][c4 * 4 + 2] = v.z;
        ts[r][c4 * 4 + 3] = v.w;
    }
    __syncthreads();
    #pragma unroll
    for (int l = 0; l < 4; l++) {
        int idx = tid + l * 256;
        int nr = idx >> 4, kc = idx & 15;
        size_t orow = (size_t)(n0 + nr) * DD + k0 + kc * 4;
        #pragma unroll
        for (int j = 0; j < 4; j++) {
            float v = ts[kc * 4 + j][nr];
            __nv_bfloat16 hb; float lw; split2(v, hb, lw);
            g_wohi[orow + j] = hb;
            g_wolo[orow + j] = __float2bfloat16(lw);
        }
    }
}

// ---------------------------------------------------------------------------
// Shared GEMM plumbing (M=128 x N=128 CTA tile, K chunks of 64, 8 warps 4Mx2N)
// ---------------------------------------------------------------------------
#define QROW 72                        // bf16 per smem row (144 B)
#define QTILE_BYTES (128 * QROW * 2)   // 18432
#define GSM_AHI 0
#define GSM_ALO (QTILE_BYTES)
#define GSM_BHI (2 * QTILE_BYTES)
#define GSM_BLO (3 * QTILE_BYTES)
#define GSM_BYTES (4 * QTILE_BYTES)

__device__ __forceinline__ void load_tile_g(
    char* smem, int dst_off, const __nv_bfloat16* __restrict__ src,
    int k0, int tid)
{
    #pragma unroll
    for (int l = 0; l < 4; l++) {
        int idx = tid + l * 256;
        int r = idx >> 3, c = idx & 7;
        float4 v = *(const float4*)((const char*)src + ((size_t)r * DD + k0) * 2 + c * 16);
        *(float4*)(smem + dst_off + r * (QROW * 2) + c * 16) = v;
    }
}

// body: 16-chunk K loop with 3-pass split; acc[2][8][4]
__device__ __forceinline__ void gemm_body(
    char* smem, uint32_t a_base, uint32_t b_base,
    const __nv_bfloat16* Ahi, const __nv_bfloat16* Alo,
    const __nv_bfloat16* Bhi, const __nv_bfloat16* Blo,
    int tid, float acc[2][8][4])
{
    for (int ch = 0; ch < 16; ch++) {
        const int k0 = ch * 64;
        if (ch) __syncthreads();
        load_tile_g(smem, GSM_AHI, Ahi, k0, tid);
        load_tile_g(smem, GSM_ALO, Alo, k0, tid);
        load_tile_g(smem, GSM_BHI, Bhi, k0, tid);
        load_tile_g(smem, GSM_BLO, Blo, k0, tid);
        __syncthreads();

        #pragma unroll
        for (int ks = 0; ks < 4; ks++) {
            const uint32_t koff = ks * 32;
            uint32_t ahi[2][4], alo[2][4];
            #pragma unroll
            for (int am = 0; am < 2; am++) {
                ldsm_x4(a_base + GSM_AHI + am * 16 * (QROW * 2) + koff, ahi[am]);
                ldsm_x4(a_base + GSM_ALO + am * 16 * (QROW * 2) + koff, alo[am]);
            }
            uint32_t bhi[4][4], blo[4][4];
            #pragma unroll
            for (int bn = 0; bn < 4; bn++) {
                ldsm_x4(b_base + GSM_BHI + bn * 16 * (QROW * 2) + koff, bhi[bn]);
                ldsm_x4(b_base + GSM_BLO + bn * 16 * (QROW * 2) + koff, blo[bn]);
            }
            #pragma unroll
            for (int am = 0; am < 2; am++) {
                #pragma unroll
                for (int bn = 0; bn < 4; bn++) {
                    mma_bf16(acc[am][2*bn],   ahi[am], bhi[bn][0], bhi[bn][2]);
                    mma_bf16(acc[am][2*bn+1], ahi[am], bhi[bn][1], bhi[bn][3]);
                    mma_bf16(acc[am][2*bn],   ahi[am], blo[bn][0], blo[bn][2]);
                    mma_bf16(acc[am][2*bn+1], ahi[am], blo[bn][1], blo[bn][3]);
                    mma_bf16(acc[am][2*bn],   alo[am], bhi[bn][0], bhi[bn][2]);
                    mma_bf16(acc[am][2*bn+1], alo[am], bhi[bn][1], bhi[bn][3]);
                }
            }
        }
    }
}

// ---------------------------------------------------------------------------
// QKV GEMM: writes Q/K/V as bf16 hi/lo (Q scaled by 1/8).
// grid (32 token tiles, 8 head-pairs, 3 proj); block 256.
// ---------------------------------------------------------------------------
__global__ __launch_bounds__(256, 1) void qkv_mma_kernel(
    const float* __restrict__ bq, const float* __restrict__ bk,
    const float* __restrict__ bv)
{
    extern __shared__ char smem[];
    const uint32_t smem_base = smem_to_u32(smem);
    const int tid  = threadIdx.x;
    const int lane = tid & 31;
    const int warpM = (tid >> 5) & 3;
    const int warpN = tid >> 7;

    const int m0   = blockIdx.x * 128;
    const int hg   = blockIdx.y;
    const int proj = blockIdx.z;

    const float* bias = (proj == 0) ? bq : (proj == 1) ? bk : bv;
    __nv_bfloat16* ohi = (proj == 0) ? g_qhi : (proj == 1) ? g_khi : g_vhi;
    __nv_bfloat16* olo = (proj == 0) ? g_qlo : (proj == 1) ? g_klo : g_vlo;
    const float scale = (proj == 0) ? 0.125f : 1.0f;

    const __nv_bfloat16* Ahi = g_xhi + (size_t)m0 * DD;
    const __nv_bfloat16* Alo = g_xlo + (size_t)m0 * DD;
    const size_t brow = ((size_t)proj * HH * DKH + (size_t)hg * 128) * DD;

    float acc[2][8][4] = {};

    const int lrow  = lane & 15;
    const int lhalf = lane >> 4;
    const uint32_t a_base = smem_base +
        (uint32_t)((warpM * 32 + lrow) * (QROW * 2) + lhalf * 16);
    const uint32_t b_base = smem_base +
        (uint32_t)((warpN * 64 + lrow) * (QROW * 2) + lhalf * 16);

    gemm_body(smem, a_base, b_base, Ahi, Alo, g_whi + brow, g_wlo + brow,
              tid, acc);

    #pragma unroll
    for (int am = 0; am < 2; am++) {
        #pragma unroll
        for (int rh = 0; rh < 2; rh++) {
            const int token = m0 + warpM * 32 + am * 16 + rh * 8 + (lane >> 2);
            const int b_ = token >> 11;
            const int s_ = token & (SS - 1);
            #pragma unroll
            for (int na = 0; na < 8; na++) {
                const int ng = hg * 128 + warpN * 64 + na * 8 + (lane & 3) * 2;
                const int h  = ng >> 6;
                const int dk = ng & 63;
                float v0 = (acc[am][na][rh*2+0] + __ldg(&bias[h*DKH + dk]))   * scale;
                float v1 = (acc[am][na][rh*2+1] + __ldg(&bias[h*DKH + dk+1])) * scale;
                __nv_bfloat16 h0, h1; float l0, l1;
                split2(v0, h0, l0); split2(v1, h1, l1);
                size_t idx = ((size_t)(b_ * HH + h) * SS + s_) * DKH + dk;
                *(__nv_bfloat162*)&ohi[idx] = __nv_bfloat162(h0, h1);
                *(__nv_bfloat162*)&olo[idx] =
                    __nv_bfloat162(__float2bfloat16(l0), __float2bfloat16(l1));
            }
        }
    }
}

// ---------------------------------------------------------------------------
// Output projection on HMMA: out = ctx @ Wo + bo (fp32 out).
// grid (32 m-tiles, 8 n-tiles); block 256.
// ---------------------------------------------------------------------------
__global__ __launch_bounds__(256, 1) void out_mma_kernel(
    const float* __restrict__ bo, float* __restrict__ out)
{
    extern __shared__ char smem[];
    const uint32_t smem_base = smem_to_u32(smem);
    const int tid  = threadIdx.x;
    const int lane = tid & 31;
    const int warpM = (tid >> 5) & 3;
    const int warpN = tid >> 7;

    const int m0 = blockIdx.x * 128;
    const int n0 = blockIdx.y * 128;

    float acc[2][8][4] = {};

    const int lrow  = lane & 15;
    const int lhalf = lane >> 4;
    const uint32_t a_base = smem_base +
        (uint32_t)((warpM * 32 + lrow) * (QROW * 2) + lhalf * 16);
    const uint32_t b_base = smem_base +
        (uint32_t)((warpN * 64 + lrow) * (QROW * 2) + lhalf * 16);

    gemm_body(smem, a_base, b_base,
              g_chi + (size_t)m0 * DD, g_clo + (size_t)m0 * DD,
              g_wohi + (size_t)n0 * DD, g_wolo + (size_t)n0 * DD,
              tid, acc);

    #pragma unroll
    for (int am = 0; am < 2; am++) {
        #pragma unroll
        for (int rh = 0; rh < 2; rh++) {
            const int token = m0 + warpM * 32 + am * 16 + rh * 8 + (lane >> 2);
            #pragma unroll
            for (int na = 0; na < 8; na++) {
                const int n = n0 + warpN * 64 + na * 8 + (lane & 3) * 2;
                float2 o;
                o.x = acc[am][na][rh*2+0] + __ldg(&bo[n]);
                o.y = acc[am][na][rh*2+1] + __ldg(&bo[n+1]);
                *(float2*)&out[(size_t)token * DD + n] = o;
            }
        }
    }
}

// ---------------------------------------------------------------------------
// Flash attention on HMMA. grid (16 q-tiles, 32 bh); block 256 (8 warps x 16q).
// Key chunks of 64; S and PV both 3-pass bf16 hi/lo.
// ---------------------------------------------------------------------------
#define AROW 72                         // bf16 per smem row (144 B)
#define ATILE (64 * AROW * 2)           // 9216 B (64-row tile)
#define ASM_KHI 0
#define ASM_KLO (ATILE)
#define ASM_VHI (2 * ATILE)
#define ASM_VLO (3 * ATILE)
// Q staging overlays the same buffer before the chunk loop
#define ASM_QHI 0
#define ASM_QLO (2 * ATILE)

__global__ __launch_bounds__(256, 1) void attn_mma_kernel()
{
    __shared__ __align__(16) char smem[4 * ATILE];
    const uint32_t smem_base = smem_to_u32(smem);
    const int tid  = threadIdx.x;
    const int lane = tid & 31;
    const int w    = tid >> 5;          // warp 0..7 -> query rows w*16..

    const int bh = blockIdx.y;
    const int q0 = blockIdx.x * 128;
    const size_t base = (size_t)bh * SS * DKH;

    const int lrow  = lane & 15;
    const int lhalf = lane >> 4;

    // ---- stage Q tile (128 x 64 hi/lo) and extract resident fragments ----
    {
        const __nv_bfloat16* Qh = g_qhi + base + (size_t)q0 * DKH;
        const __nv_bfloat16* Ql = g_qlo + base + (size_t)q0 * DKH;
        #pragma unroll
        for (int l = 0; l < 4; l++) {
            int idx = tid + l * 256;
            int r = idx >> 3, c = idx & 7;   // 128 rows x 8 chunks
            *(float4*)(smem + ASM_QHI + r * (AROW*2) + c * 16) =
                *(const float4*)((const char*)Qh + ((size_t)r * DKH) * 2 + c * 16);
            *(float4*)(smem + ASM_QLO + r * (AROW*2) + c * 16) =
                *(const float4*)((const char*)Ql + ((size_t)r * DKH) * 2 + c * 16);
        }
    }
    __syncthreads();

    uint32_t qhi[4][4], qlo[4][4];
    {
        const uint32_t qa = smem_base + (uint32_t)((w * 16 + lrow) * (AROW*2) + lhalf * 16);
        #pragma unroll
        for (int ks = 0; ks < 4; ks++) {
            ldsm_x4(qa + ASM_QHI + ks * 32, qhi[ks]);
            ldsm_x4(qa + ASM_QLO + ks * 32, qlo[ks]);
        }
    }
    __syncthreads();

    float o[8][4] = {};
    float mA = -1e30f, mB = -1e30f, lA = 0.0f, lB = 0.0f;

    const uint32_t kb = smem_base + (uint32_t)(lrow * (AROW*2) + lhalf * 16);

    for (int ch = 0; ch < 32; ch++) {
        const size_t key0 = base + (size_t)(ch * 64) * DKH;
        // load K/V hi+lo 64x64 tiles
        #pragma unroll
        for (int l = 0; l < 2; l++) {
            int idx = tid + l * 256;
            int r = idx >> 3, c = idx & 7;
            size_t so = ((size_t)r * DKH) * 2 + c * 16;
            uint32_t dof = (uint32_t)(r * (AROW*2) + c * 16);
            *(float4*)(smem + ASM_KHI + dof) = *(const float4*)((const char*)(g_khi + key0) + so);
            *(float4*)(smem + ASM_KLO + dof) = *(const float4*)((const char*)(g_klo + key0) + so);
            *(float4*)(smem + ASM_VHI + dof) = *(const float4*)((const char*)(g_vhi + key0) + so);
            *(float4*)(smem + ASM_VLO + dof) = *(const float4*)((const char*)(g_vlo + key0) + so);
        }
        __syncthreads();

        // ---- S = Q K^T : 16 x 64 per warp, 3-pass ----
        float s[8][4] = {};
        #pragma unroll
        for (int ks = 0; ks < 4; ks++) {
            const uint32_t koff = ks * 32;
            #pragma unroll
            for (int bn = 0; bn < 4; bn++) {
                uint32_t kh[4], kl[4];
                ldsm_x4(kb + ASM_KHI + bn * 16 * (AROW*2) + koff, kh);
                ldsm_x4(kb + ASM_KLO + bn * 16 * (AROW*2) + koff, kl);
                mma_bf16(s[2*bn],   qhi[ks], kh[0], kh[2]);
                mma_bf16(s[2*bn+1], qhi[ks], kh[1], kh[3]);
                mma_bf16(s[2*bn],   qhi[ks], kl[0], kl[2]);
                mma_bf16(s[2*bn+1], qhi[ks], kl[1], kl[3]);
                mma_bf16(s[2*bn],   qlo[ks], kh[0], kh[2]);
                mma_bf16(s[2*bn+1], qlo[ks], kh[1], kh[3]);
            }
        }

        // ---- online softmax (rows lane>>2 and +8; reduce over 4-lane quad) --
        float mxA = -1e30f, mxB = -1e30f;
        #pragma unroll
        for (int j = 0; j < 8; j++) {
            mxA = fmaxf(mxA, fmaxf(s[j][0], s[j][1]));
            mxB = fmaxf(mxB, fmaxf(s[j][2], s[j][3]));
        }
        #pragma unroll
        for (int msk = 1; msk < 4; msk <<= 1) {
            mxA = fmaxf(mxA, __shfl_xor_sync(0xffffffffu, mxA, msk));
            mxB = fmaxf(mxB, __shfl_xor_sync(0xffffffffu, mxB, msk));
        }
        const float mnA = fmaxf(mA, mxA);
        const float mnB = fmaxf(mB, mxB);
        const float fA = __expf(mA - mnA);
        const float fB = __expf(mB - mnB);
        mA = mnA; mB = mnB;
        float rsA = 0.0f, rsB = 0.0f;
        #pragma unroll
        for (int j = 0; j < 8; j++) {
            s[j][0] = __expf(s[j][0] - mnA); rsA += s[j][0];
            s[j][1] = __expf(s[j][1] - mnA); rsA += s[j][1];
            s[j][2] = __expf(s[j][2] - mnB); rsB += s[j][2];
            s[j][3] = __expf(s[j][3] - mnB); rsB += s[j][3];
        }
        #pragma unroll
        for (int msk = 1; msk < 4; msk <<= 1) {
            rsA += __shfl_xor_sync(0xffffffffu, rsA, msk);
            rsB += __shfl_xor_sync(0xffffffffu, rsB, msk);
        }
        lA = lA * fA + rsA;
        lB = lB * fB + rsB;
        #pragma unroll
        for (int j = 0; j < 8; j++) {
            o[j][0] *= fA; o[j][1] *= fA;
            o[j][2] *= fB; o[j][3] *= fB;
        }

        // ---- O += P V : P split hi/lo in registers, V via ldmatrix.trans ----
        #pragma unroll
        for (int j = 0; j < 4; j++) {
            // P a-frags from S tiles 2j, 2j+1
            uint32_t ph[4], pl[4];
            {
                __nv_bfloat16 hb[8]; float lw[8];
                split2(s[2*j][0],   hb[0], lw[0]);
                split2(s[2*j][1],   hb[1], lw[1]);
                split2(s[2*j][2],   hb[2], lw[2]);
                split2(s[2*j][3],   hb[3], lw[3]);
                split2(s[2*j+1][0], hb[4], lw[4]);
                split2(s[2*j+1][1], hb[5], lw[5]);
                split2(s[2*j+1][2], hb[6], lw[6]);
                split2(s[2*j+1][3], hb[7], lw[7]);
                union { __nv_bfloat162 b2; uint32_t u; } t;
                t.b2 = __nv_bfloat162(hb[0], hb[1]); ph[0] = t.u;
                t.b2 = __nv_bfloat162(hb[2], hb[3]); ph[1] = t.u;
                t.b2 = __nv_bfloat162(hb[4], hb[5]); ph[2] = t.u;
                t.b2 = __nv_bfloat162(hb[6], hb[7]); ph[3] = t.u;
                pl[0] = pkbf(lw[0], lw[1]);
                pl[1] = pkbf(lw[2], lw[3]);
                pl[2] = pkbf(lw[4], lw[5]);
                pl[3] = pkbf(lw[6], lw[7]);
            }
            const uint32_t vrow = (uint32_t)((j * 16 + lrow) * (AROW*2) + lhalf * 16);
            #pragma unroll
            for (int dvp = 0; dvp < 4; dvp++) {
                uint32_t vh[4], vl[4];
                ldsm_x4_t(smem_base + ASM_VHI + vrow + dvp * 32, vh);
                ldsm_x4_t(smem_base + ASM_VLO + vrow + dvp * 32, vl);
                mma_bf16(o[2*dvp],   ph, vh[0], vh[1]);
                mma_bf16(o[2*dvp+1], ph, vh[2], vh[3]);
                mma_bf16(o[2*dvp],   ph, vl[0], vl[1]);
                mma_bf16(o[2*dvp+1], ph, vl[2], vl[3]);
                mma_bf16(o[2*dvp],   pl, vh[0], vh[1]);
                mma_bf16(o[2*dvp+1], pl, vh[2], vh[3]);
            }
        }
        __syncthreads();
    }

    // ---- epilogue: normalize, split hi/lo, write ctx [token][1024] ----
    const int b_ = bh / HH;
    const int h_ = bh % HH;
    const float invA = 1.0f / lA;
    const float invB = 1.0f / lB;
    const int rA = q0 + w * 16 + (lane >> 2);
    const int tokenA = b_ * SS + rA;
    const int tokenB = tokenA + 8;
    #pragma unroll
    for (int jj = 0; jj < 8; jj++) {
        const int col = h_ * DKH + jj * 8 + (lane & 3) * 2;
        {
            float v0 = o[jj][0] * invA, v1 = o[jj][1] * invA;
            __nv_bfloat16 h0, h1; float l0, l1;
            split2(v0, h0, l0); split2(v1, h1, l1);
            size_t idx = (size_t)tokenA * DD + col;
            *(__nv_bfloat162*)&g_chi[idx] = __nv_bfloat162(h0, h1);
            *(__nv_bfloat162*)&g_clo[idx] =
                __nv_bfloat162(__float2bfloat16(l0), __float2bfloat16(l1));
        }
        {
            float v0 = o[jj][2] * invB, v1 = o[jj][3] * invB;
            __nv_bfloat16 h0, h1; float l0, l1;
            split2(v0, h0, l0); split2(v1, h1, l1);
            size_t idx = (size_t)tokenB * DD + col;
            *(__nv_bfloat162*)&g_chi[idx] = __nv_bfloat162(h0, h1);
            *(__nv_bfloat162*)&g_clo[idx] =
                __nv_bfloat162(__float2bfloat16(l0), __float2bfloat16(l1));
        }
    }
}

// ---------------------------------------------------------------------------
extern "C" void kernel_launch(void* const* d_in, const int* in_sizes, int n_in,
                              void* d_out, int out_size)
{
    const float* X  = (const float*)d_in[0];
    const float* Wq = (const float*)d_in[1];
    const float* bq = (const float*)d_in[2];
    const float* Wk = (const float*)d_in[3];
    const float* bk = (const float*)d_in[4];
    const float* Wv = (const float*)d_in[5];
    const float* bv = (const float*)d_in[6];
    const float* Wo = (const float*)d_in[7];
    const float* bo = (const float*)d_in[8];
    float* out = (float*)d_out;

    cudaFuncSetAttribute(qkv_mma_kernel,
                         cudaFuncAttributeMaxDynamicSharedMemorySize, GSM_BYTES);
    cudaFuncSetAttribute(out_mma_kernel,
                         cudaFuncAttributeMaxDynamicSharedMemorySize, GSM_BYTES);

    conv_x_kernel<<<2048, 256>>>((const float4*)X);
    conv_w_kernel<<<dim3(16, 16, 3), 256>>>(Wq, Wk, Wv);
    conv_wo_kernel<<<dim3(16, 16), 256>>>(Wo);
    qkv_mma_kernel<<<dim3(32, 8, 3), 256, GSM_BYTES>>>(bq, bk, bv);
    attn_mma_kernel<<<dim3(16, 32), 256>>>();
    out_mma_kernel<<<dim3(32, 8), 256, GSM_BYTES>>>(bo, out);
}

// round 6
// speedup vs baseline: 2.3468x; 1.0196x over previous
#include <cuda_runtime.h>
#include <cuda_bf16.h>
#include <cstdint>

#define BB 2
#define SS 2048
#define DD 1024
#define HH 16
#define DKH 64
#define BHH (BB*HH)

// ---------------------------------------------------------------------------
// Scratch (allocation-free rule: __device__ globals) — all bf16 hi/lo pairs
// ---------------------------------------------------------------------------
__device__ __nv_bfloat16 g_xhi[BB * SS * DD];
__device__ __nv_bfloat16 g_xlo[BB * SS * DD];
__device__ __nv_bfloat16 g_whi[3 * HH * DKH * DD];   // [(proj*16+h)*64+n][k]
__device__ __nv_bfloat16 g_wlo[3 * HH * DKH * DD];
__device__ __nv_bfloat16 g_qhi[BHH * SS * DKH];      // [bh][s][64] (x 1/8)
__device__ __nv_bfloat16 g_qlo[BHH * SS * DKH];
__device__ __nv_bfloat16 g_khi[BHH * SS * DKH];
__device__ __nv_bfloat16 g_klo[BHH * SS * DKH];
__device__ __nv_bfloat16 g_vhi[BHH * SS * DKH];
__device__ __nv_bfloat16 g_vlo[BHH * SS * DKH];
__device__ __nv_bfloat16 g_chi[BB * SS * HH * DKH];  // ctx [token][1024]
__device__ __nv_bfloat16 g_clo[BB * SS * HH * DKH];
__device__ __nv_bfloat16 g_wohi[DD * DD];            // Wo^T [n][k]
__device__ __nv_bfloat16 g_wolo[DD * DD];

// ---------------------------------------------------------------------------
// Helpers
// ---------------------------------------------------------------------------
__device__ __forceinline__ uint32_t smem_to_u32(const void* p) {
    uint32_t a;
    asm("{ .reg .u64 t; cvta.to.shared.u64 t, %1; cvt.u32.u64 %0, t; }"
        : "=r"(a) : "l"(p));
    return a;
}
__device__ __forceinline__ void ldsm_x4(uint32_t addr, uint32_t* r) {
    asm volatile("ldmatrix.sync.aligned.m8n8.x4.shared.b16 {%0,%1,%2,%3}, [%4];"
        : "=r"(r[0]), "=r"(r[1]), "=r"(r[2]), "=r"(r[3]) : "r"(addr));
}
__device__ __forceinline__ void ldsm_x4_t(uint32_t addr, uint32_t* r) {
    asm volatile("ldmatrix.sync.aligned.m8n8.x4.trans.shared.b16 {%0,%1,%2,%3}, [%4];"
        : "=r"(r[0]), "=r"(r[1]), "=r"(r[2]), "=r"(r[3]) : "r"(addr));
}
__device__ __forceinline__ void mma_bf16(float* d, const uint32_t* a,
                                         uint32_t b0, uint32_t b1) {
    asm volatile(
        "mma.sync.aligned.m16n8k16.row.col.f32.bf16.bf16.f32 "
        "{%0,%1,%2,%3}, {%4,%5,%6,%7}, {%8,%9}, {%0,%1,%2,%3};"
        : "+f"(d[0]), "+f"(d[1]), "+f"(d[2]), "+f"(d[3])
        : "r"(a[0]), "r"(a[1]), "r"(a[2]), "r"(a[3]), "r"(b0), "r"(b1));
}
__device__ __forceinline__ uint32_t pkbf(float lo, float hi) {
    uint32_t r;
    asm("cvt.rn.bf16x2.f32 %0, %1, %2;" : "=r"(r) : "f"(hi), "f"(lo));
    return r;
}
__device__ __forceinline__ void split2(float v, __nv_bfloat16& h, float& l) {
    h = __float2bfloat16(v);
    l = v - __bfloat162float(h);
}
__device__ __forceinline__ void cpasync16(uint32_t dst, const void* src) {
    asm volatile("cp.async.cg.shared.global [%0], [%1], 16;"
                 :: "r"(dst), "l"(src));
}
#define CP_COMMIT() asm volatile("cp.async.commit_group;" ::: "memory")
#define CP_WAIT1()  asm volatile("cp.async.wait_group 1;" ::: "memory")
#define CP_WAIT0()  asm volatile("cp.async.wait_group 0;" ::: "memory")

// ---------------------------------------------------------------------------
// Prep A: split X into bf16 hi/lo.
// ---------------------------------------------------------------------------
__global__ __launch_bounds__(256) void conv_x_kernel(const float4* __restrict__ X4)
{
    int i0 = blockIdx.x * 256 + threadIdx.x;
    #pragma unroll
    for (int l = 0; l < 2; l++) {
        int i = i0 + l * 524288;
        float4 v = X4[i];
        float vv[4] = {v.x, v.y, v.z, v.w};
        union { float2 f; __nv_bfloat16 h[4]; } hi, lo;
        #pragma unroll
        for (int j = 0; j < 4; j++) {
            float lw; split2(vv[j], hi.h[j], lw);
            lo.h[j] = __float2bfloat16(lw);
        }
        ((float2*)g_xhi)[i] = hi.f;
        ((float2*)g_xlo)[i] = lo.f;
    }
}

// ---------------------------------------------------------------------------
// Prep B: transpose + split Wq/Wk/Wv.
// ---------------------------------------------------------------------------
__global__ __launch_bounds__(256) void conv_w_kernel(
    const float* __restrict__ Wq, const float* __restrict__ Wk,
    const float* __restrict__ Wv)
{
    __shared__ float ts[64][65];
    const int k0   = blockIdx.x * 64;
    const int h    = blockIdx.y;
    const int proj = blockIdx.z;
    const float* W = (proj == 0) ? Wq : (proj == 1) ? Wk : Wv;
    W += (size_t)h * DD * DKH;

    const int tid = threadIdx.x;
    #pragma unroll
    for (int l = 0; l < 4; l++) {
        int idx = tid + l * 256;
        int r = idx >> 4, c4 = idx & 15;
        float4 v = *(const float4*)&W[(size_t)(k0 + r) * DKH + c4 * 4];
        ts[r][c4 * 4 + 0] = v.x;
        ts[r][c4 * 4 + 1] = v.y;
        ts[r][c4 * 4 + 2] = v.z;
        ts[r][c4 * 4 + 3] = v.w;
    }
    __syncthreads();
    #pragma unroll
    for (int l = 0; l < 4; l++) {
        int idx = tid + l * 256;
        int nr = idx >> 4, kc = idx & 15;
        size_t orow = ((size_t)(proj * HH + h) * DKH + nr) * DD + k0 + kc * 4;
        #pragma unroll
        for (int j = 0; j < 4; j++) {
            float v = ts[kc * 4 + j][nr];
            __nv_bfloat16 hb; float lw; split2(v, hb, lw);
            g_whi[orow + j] = hb;
            g_wlo[orow + j] = __float2bfloat16(lw);
        }
    }
}

// ---------------------------------------------------------------------------
// Prep C: transpose + split Wo.
// ---------------------------------------------------------------------------
__global__ __launch_bounds__(256) void conv_wo_kernel(const float* __restrict__ Wo)
{
    __shared__ float ts[64][65];
    const int k0 = blockIdx.x * 64;
    const int n0 = blockIdx.y * 64;
    const int tid = threadIdx.x;
    #pragma unroll
    for (int l = 0; l < 4; l++) {
        int idx = tid + l * 256;
        int r = idx >> 4, c4 = idx & 15;
        float4 v = *(const float4*)&Wo[(size_t)(k0 + r) * DD + n0 + c4 * 4];
        ts[r][c4 * 4 + 0] = v.x;
        ts[r][c4 * 4 + 1] = v.y;
        ts[r][c4 * 4 + 2] = v.z;
        ts[r][c4 * 4 + 3] = v.w;
    }
    __syncthreads();
    #pragma unroll
    for (int l = 0; l < 4; l++) {
        int idx = tid + l * 256;
        int nr = idx >> 4, kc = idx & 15;
        size_t orow = (size_t)(n0 + nr) * DD + k0 + kc * 4;
        #pragma unroll
        for (int j = 0; j < 4; j++) {
            float v = ts[kc * 4 + j][nr];
            __nv_bfloat16 hb; float lw; split2(v, hb, lw);
            g_wohi[orow + j] = hb;
            g_wolo[orow + j] = __float2bfloat16(lw);
        }
    }
}

// ---------------------------------------------------------------------------
// Pipelined GEMM plumbing: M128 x N128 CTA tile, K chunks of 32, 2 stages.
// Row stride 80B (conflict-free for ldmatrix with 128B bank wrap).
// ---------------------------------------------------------------------------
#define CROWB 80
#define CTILE (128 * CROWB)       // 10240
#define CSTAGE (4 * CTILE)        // 40960 : AHI | ALO | BHI | BLO
#define GSM_BYTES (2 * CSTAGE)    // 81920

__device__ __forceinline__ void load_stage_g(
    uint32_t sm,
    const __nv_bfloat16* __restrict__ Ahi, const __nv_bfloat16* __restrict__ Alo,
    const __nv_bfloat16* __restrict__ Bhi, const __nv_bfloat16* __restrict__ Blo,
    int k0, int tid)
{
    #pragma unroll
    for (int l = 0; l < 2; l++) {
        int idx = tid + l * 256;
        int r = idx >> 2, c = idx & 3;
        uint32_t dof = (uint32_t)(r * CROWB + c * 16);
        size_t   sof = ((size_t)r * DD + k0) * 2 + c * 16;
        cpasync16(sm + 0 * CTILE + dof, (const char*)Ahi + sof);
        cpasync16(sm + 1 * CTILE + dof, (const char*)Alo + sof);
        cpasync16(sm + 2 * CTILE + dof, (const char*)Bhi + sof);
        cpasync16(sm + 3 * CTILE + dof, (const char*)Blo + sof);
    }
}

__device__ __forceinline__ void gemm_body(
    uint32_t smem_base, uint32_t a_lane, uint32_t b_lane,
    const __nv_bfloat16* Ahi, const __nv_bfloat16* Alo,
    const __nv_bfloat16* Bhi, const __nv_bfloat16* Blo,
    int tid, float acc[2][8][4])
{
    load_stage_g(smem_base, Ahi, Alo, Bhi, Blo, 0, tid);
    CP_COMMIT();
    load_stage_g(smem_base + CSTAGE, Ahi, Alo, Bhi, Blo, 32, tid);
    CP_COMMIT();

    for (int ch = 0; ch < 32; ch++) {
        if (ch >= 30) { CP_WAIT0(); } else { CP_WAIT1(); }
        __syncthreads();
        const uint32_t st = smem_base + (uint32_t)(ch & 1) * CSTAGE;

        #pragma unroll
        for (int ks = 0; ks < 2; ks++) {
            const uint32_t koff = ks * 32;
            uint32_t ahi[2][4], alo[2][4];
            #pragma unroll
            for (int am = 0; am < 2; am++) {
                ldsm_x4(st + 0 * CTILE + a_lane + am * 16 * CROWB + koff, ahi[am]);
                ldsm_x4(st + 1 * CTILE + a_lane + am * 16 * CROWB + koff, alo[am]);
            }
            uint32_t bhi[4][4], blo[4][4];
            #pragma unroll
            for (int bn = 0; bn < 4; bn++) {
                ldsm_x4(st + 2 * CTILE + b_lane + bn * 16 * CROWB + koff, bhi[bn]);
                ldsm_x4(st + 3 * CTILE + b_lane + bn * 16 * CROWB + koff, blo[bn]);
            }
            #pragma unroll
            for (int am = 0; am < 2; am++) {
                #pragma unroll
                for (int bn = 0; bn < 4; bn++) {
                    mma_bf16(acc[am][2*bn],   ahi[am], bhi[bn][0], bhi[bn][2]);
                    mma_bf16(acc[am][2*bn+1], ahi[am], bhi[bn][1], bhi[bn][3]);
                    mma_bf16(acc[am][2*bn],   ahi[am], blo[bn][0], blo[bn][2]);
                    mma_bf16(acc[am][2*bn+1], ahi[am], blo[bn][1], blo[bn][3]);
                    mma_bf16(acc[am][2*bn],   alo[am], bhi[bn][0], bhi[bn][2]);
                    mma_bf16(acc[am][2*bn+1], alo[am], bhi[bn][1], bhi[bn][3]);
                }
            }
        }
        __syncthreads();
        if (ch + 2 < 32) {
            load_stage_g(smem_base + (uint32_t)(ch & 1) * CSTAGE,
                         Ahi, Alo, Bhi, Blo, (ch + 2) * 32, tid);
            CP_COMMIT();
        }
    }
}

// ---------------------------------------------------------------------------
// QKV GEMM: writes Q/K/V as bf16 hi/lo (Q scaled by 1/8).
// ---------------------------------------------------------------------------
__global__ __launch_bounds__(256, 1) void qkv_mma_kernel(
    const float* __restrict__ bq, const float* __restrict__ bk,
    const float* __restrict__ bv)
{
    extern __shared__ char smem[];
    const uint32_t smem_base = smem_to_u32(smem);
    const int tid  = threadIdx.x;
    const int lane = tid & 31;
    const int warpM = (tid >> 5) & 3;
    const int warpN = tid >> 7;

    const int m0   = blockIdx.x * 128;
    const int hg   = blockIdx.y;
    const int proj = blockIdx.z;

    const float* bias = (proj == 0) ? bq : (proj == 1) ? bk : bv;
    __nv_bfloat16* ohi = (proj == 0) ? g_qhi : (proj == 1) ? g_khi : g_vhi;
    __nv_bfloat16* olo = (proj == 0) ? g_qlo : (proj == 1) ? g_klo : g_vlo;
    const float scale = (proj == 0) ? 0.125f : 1.0f;

    const size_t brow = ((size_t)proj * HH * DKH + (size_t)hg * 128) * DD;

    float acc[2][8][4] = {};

    const int lrow  = lane & 15;
    const int lhalf = lane >> 4;
    const uint32_t a_lane = (uint32_t)((warpM * 32 + lrow) * CROWB + lhalf * 16);
    const uint32_t b_lane = (uint32_t)((warpN * 64 + lrow) * CROWB + lhalf * 16);

    gemm_body(smem_base, a_lane, b_lane,
              g_xhi + (size_t)m0 * DD, g_xlo + (size_t)m0 * DD,
              g_whi + brow, g_wlo + brow, tid, acc);

    #pragma unroll
    for (int am = 0; am < 2; am++) {
        #pragma unroll
        for (int rh = 0; rh < 2; rh++) {
            const int token = m0 + warpM * 32 + am * 16 + rh * 8 + (lane >> 2);
            const int b_ = token >> 11;
            const int s_ = token & (SS - 1);
            #pragma unroll
            for (int na = 0; na < 8; na++) {
                const int ng = hg * 128 + warpN * 64 + na * 8 + (lane & 3) * 2;
                const int h  = ng >> 6;
                const int dk = ng & 63;
                float v0 = (acc[am][na][rh*2+0] + __ldg(&bias[h*DKH + dk]))   * scale;
                float v1 = (acc[am][na][rh*2+1] + __ldg(&bias[h*DKH + dk+1])) * scale;
                __nv_bfloat16 h0, h1; float l0, l1;
                split2(v0, h0, l0); split2(v1, h1, l1);
                size_t idx = ((size_t)(b_ * HH + h) * SS + s_) * DKH + dk;
                *(__nv_bfloat162*)&ohi[idx] = __nv_bfloat162(h0, h1);
                *(__nv_bfloat162*)&olo[idx] =
                    __nv_bfloat162(__float2bfloat16(l0), __float2bfloat16(l1));
            }
        }
    }
}

// ---------------------------------------------------------------------------
// Output projection: out = ctx @ Wo + bo (fp32 out).
// ---------------------------------------------------------------------------
__global__ __launch_bounds__(256, 1) void out_mma_kernel(
    const float* __restrict__ bo, float* __restrict__ out)
{
    extern __shared__ char smem[];
    const uint32_t smem_base = smem_to_u32(smem);
    const int tid  = threadIdx.x;
    const int lane = tid & 31;
    const int warpM = (tid >> 5) & 3;
    const int warpN = tid >> 7;

    const int m0 = blockIdx.x * 128;
    const int n0 = blockIdx.y * 128;

    float acc[2][8][4] = {};

    const int lrow  = lane & 15;
    const int lhalf = lane >> 4;
    const uint32_t a_lane = (uint32_t)((warpM * 32 + lrow) * CROWB + lhalf * 16);
    const uint32_t b_lane = (uint32_t)((warpN * 64 + lrow) * CROWB + lhalf * 16);

    gemm_body(smem_base, a_lane, b_lane,
              g_chi + (size_t)m0 * DD, g_clo + (size_t)m0 * DD,
              g_wohi + (size_t)n0 * DD, g_wolo + (size_t)n0 * DD, tid, acc);

    #pragma unroll
    for (int am = 0; am < 2; am++) {
        #pragma unroll
        for (int rh = 0; rh < 2; rh++) {
            const int token = m0 + warpM * 32 + am * 16 + rh * 8 + (lane >> 2);
            #pragma unroll
            for (int na = 0; na < 8; na++) {
                const int n = n0 + warpN * 64 + na * 8 + (lane & 3) * 2;
                float2 o;
                o.x = acc[am][na][rh*2+0] + __ldg(&bo[n]);
                o.y = acc[am][na][rh*2+1] + __ldg(&bo[n+1]);
                *(float2*)&out[(size_t)token * DD + n] = o;
            }
        }
    }
}

// ---------------------------------------------------------------------------
// Flash attention, pipelined. grid (16 q-tiles, 32 bh); block 256.
// Key chunks of 64; 2-stage cp.async K/V tiles.
// ---------------------------------------------------------------------------
#define AROWB 144                    // 72 bf16 per row
#define ATILE (64 * AROWB)           // 9216
#define AST (4 * ATILE)              // 36864 : KHI | KLO | VHI | VLO
#define ATTN_SM_BYTES (2 * AST)      // 73728

__device__ __forceinline__ void attn_load_stage(
    uint32_t sm, size_t key0, int tid)
{
    #pragma unroll
    for (int l = 0; l < 2; l++) {
        int idx = tid + l * 256;
        int r = idx >> 3, c = idx & 7;
        uint32_t dof = (uint32_t)(r * AROWB + c * 16);
        size_t   sof = ((size_t)r * DKH) * 2 + c * 16;
        cpasync16(sm + 0 * ATILE + dof, (const char*)(g_khi + key0) + sof);
        cpasync16(sm + 1 * ATILE + dof, (const char*)(g_klo + key0) + sof);
        cpasync16(sm + 2 * ATILE + dof, (const char*)(g_vhi + key0) + sof);
        cpasync16(sm + 3 * ATILE + dof, (const char*)(g_vlo + key0) + sof);
    }
}

__global__ __launch_bounds__(256, 1) void attn_mma_kernel()
{
    extern __shared__ char smem[];
    const uint32_t smem_base = smem_to_u32(smem);
    const int tid  = threadIdx.x;
    const int lane = tid & 31;
    const int w    = tid >> 5;

    const int bh = blockIdx.y;
    const int q0 = blockIdx.x * 128;
    const size_t base = (size_t)bh * SS * DKH;

    const int lrow  = lane & 15;
    const int lhalf = lane >> 4;

    // ---- stage Q (128 x 64 hi/lo) into stage-1 region via cp.async ----
    {
        const __nv_bfloat16* Qh = g_qhi + base + (size_t)q0 * DKH;
        const __nv_bfloat16* Ql = g_qlo + base + (size_t)q0 * DKH;
        #pragma unroll
        for (int l = 0; l < 4; l++) {
            int idx = tid + l * 256;
            int r = idx >> 3, c = idx & 7;
            uint32_t dof = (uint32_t)(r * AROWB + c * 16);
            size_t   sof = ((size_t)r * DKH) * 2 + c * 16;
            cpasync16(smem_base + AST + dof,          (const char*)Qh + sof);
            cpasync16(smem_base + AST + 2*ATILE + dof,(const char*)Ql + sof);
        }
        CP_COMMIT();
        CP_WAIT0();
    }
    __syncthreads();

    uint32_t qhi[4][4], qlo[4][4];
    {
        const uint32_t qa = smem_base + AST +
            (uint32_t)((w * 16 + lrow) * AROWB + lhalf * 16);
        #pragma unroll
        for (int ks = 0; ks < 4; ks++) {
            ldsm_x4(qa + ks * 32, qhi[ks]);
            ldsm_x4(qa + 2*ATILE + ks * 32, qlo[ks]);
        }
    }
    // prefetch chunk 0 into stage 0 (doesn't touch Q region)
    attn_load_stage(smem_base, base, tid);
    CP_COMMIT();
    __syncthreads();     // all warps done reading Q from stage-1 region
    // prefetch chunk 1 into stage 1
    attn_load_stage(smem_base + AST, base + (size_t)64 * DKH, tid);
    CP_COMMIT();

    float o[8][4] = {};
    float mA = -1e30f, mB = -1e30f, lA = 0.0f, lB = 0.0f;

    const uint32_t lane_off = (uint32_t)(lrow * AROWB + lhalf * 16);

    for (int ch = 0; ch < 32; ch++) {
        if (ch >= 30) { CP_WAIT0(); } else { CP_WAIT1(); }
        __syncthreads();
        const uint32_t st = smem_base + (uint32_t)(ch & 1) * AST;
        const uint32_t kb = st + lane_off;

        // ---- S = Q K^T : 16 x 64 per warp, 3-pass ----
        float s[8][4] = {};
        #pragma unroll
        for (int ks = 0; ks < 4; ks++) {
            const uint32_t koff = ks * 32;
            #pragma unroll
            for (int bn = 0; bn < 4; bn++) {
                uint32_t kh[4], kl[4];
                ldsm_x4(kb + 0 * ATILE + bn * 16 * AROWB + koff, kh);
                ldsm_x4(kb + 1 * ATILE + bn * 16 * AROWB + koff, kl);
                mma_bf16(s[2*bn],   qhi[ks], kh[0], kh[2]);
                mma_bf16(s[2*bn+1], qhi[ks], kh[1], kh[3]);
                mma_bf16(s[2*bn],   qhi[ks], kl[0], kl[2]);
                mma_bf16(s[2*bn+1], qhi[ks], kl[1], kl[3]);
                mma_bf16(s[2*bn],   qlo[ks], kh[0], kh[2]);
                mma_bf16(s[2*bn+1], qlo[ks], kh[1], kh[3]);
            }
        }

        // ---- online softmax ----
        float mxA = -1e30f, mxB = -1e30f;
        #pragma unroll
        for (int j = 0; j < 8; j++) {
            mxA = fmaxf(mxA, fmaxf(s[j][0], s[j][1]));
            mxB = fmaxf(mxB, fmaxf(s[j][2], s[j][3]));
        }
        #pragma unroll
        for (int msk = 1; msk < 4; msk <<= 1) {
            mxA = fmaxf(mxA, __shfl_xor_sync(0xffffffffu, mxA, msk));
            mxB = fmaxf(mxB, __shfl_xor_sync(0xffffffffu, mxB, msk));
        }
        const float mnA = fmaxf(mA, mxA);
        const float mnB = fmaxf(mB, mxB);
        const float fA = __expf(mA - mnA);
        const float fB = __expf(mB - mnB);
        mA = mnA; mB = mnB;
        float rsA = 0.0f, rsB = 0.0f;
        #pragma unroll
        for (int j = 0; j < 8; j++) {
            s[j][0] = __expf(s[j][0] - mnA); rsA += s[j][0];
            s[j][1] = __expf(s[j][1] - mnA); rsA += s[j][1];
            s[j][2] = __expf(s[j][2] - mnB); rsB += s[j][2];
            s[j][3] = __expf(s[j][3] - mnB); rsB += s[j][3];
        }
        #pragma unroll
        for (int msk = 1; msk < 4; msk <<= 1) {
            rsA += __shfl_xor_sync(0xffffffffu, rsA, msk);
            rsB += __shfl_xor_sync(0xffffffffu, rsB, msk);
        }
        lA = lA * fA + rsA;
        lB = lB * fB + rsB;
        #pragma unroll
        for (int j = 0; j < 8; j++) {
            o[j][0] *= fA; o[j][1] *= fA;
            o[j][2] *= fB; o[j][3] *= fB;
        }

        // ---- O += P V ----
        #pragma unroll
        for (int j = 0; j < 4; j++) {
            uint32_t ph[4], pl[4];
            {
                __nv_bfloat16 hb[8]; float lw[8];
                split2(s[2*j][0],   hb[0], lw[0]);
                split2(s[2*j][1],   hb[1], lw[1]);
                split2(s[2*j][2],   hb[2], lw[2]);
                split2(s[2*j][3],   hb[3], lw[3]);
                split2(s[2*j+1][0], hb[4], lw[4]);
                split2(s[2*j+1][1], hb[5], lw[5]);
                split2(s[2*j+1][2], hb[6], lw[6]);
                split2(s[2*j+1][3], hb[7], lw[7]);
                union { __nv_bfloat162 b2; uint32_t u; } t;
                t.b2 = __nv_bfloat162(hb[0], hb[1]); ph[0] = t.u;
                t.b2 = __nv_bfloat162(hb[2], hb[3]); ph[1] = t.u;
                t.b2 = __nv_bfloat162(hb[4], hb[5]); ph[2] = t.u;
                t.b2 = __nv_bfloat162(hb[6], hb[7]); ph[3] = t.u;
                pl[0] = pkbf(lw[0], lw[1]);
                pl[1] = pkbf(lw[2], lw[3]);
                pl[2] = pkbf(lw[4], lw[5]);
                pl[3] = pkbf(lw[6], lw[7]);
            }
            const uint32_t vrow = st + (uint32_t)((j * 16 + lrow) * AROWB + lhalf * 16);
            #pragma unroll
            for (int dvp = 0; dvp < 4; dvp++) {
                uint32_t vh[4], vl[4];
                ldsm_x4_t(vrow + 2 * ATILE + dvp * 32, vh);
                ldsm_x4_t(vrow + 3 * ATILE + dvp * 32, vl);
                mma_bf16(o[2*dvp],   ph, vh[0], vh[1]);
                mma_bf16(o[2*dvp+1], ph, vh[2], vh[3]);
                mma_bf16(o[2*dvp],   ph, vl[0], vl[1]);
                mma_bf16(o[2*dvp+1], ph, vl[2], vl[3]);
                mma_bf16(o[2*dvp],   pl, vh[0], vh[1]);
                mma_bf16(o[2*dvp+1], pl, vh[2], vh[3]);
            }
        }
        __syncthreads();
        if (ch + 2 < 32) {
            attn_load_stage(smem_base + (uint32_t)(ch & 1) * AST,
                            base + (size_t)((ch + 2) * 64) * DKH, tid);
            CP_COMMIT();
        }
    }

    // ---- epilogue ----
    const int b_ = bh / HH;
    const int h_ = bh % HH;
    const float invA = 1.0f / lA;
    const float invB = 1.0f / lB;
    const int rA = q0 + w * 16 + (lane >> 2);
    const int tokenA = b_ * SS + rA;
    const int tokenB = tokenA + 8;
    #pragma unroll
    for (int jj = 0; jj < 8; jj++) {
        const int col = h_ * DKH + jj * 8 + (lane & 3) * 2;
        {
            float v0 = o[jj][0] * invA, v1 = o[jj][1] * invA;
            __nv_bfloat16 h0, h1; float l0, l1;
            split2(v0, h0, l0); split2(v1, h1, l1);
            size_t idx = (size_t)tokenA * DD + col;
            *(__nv_bfloat162*)&g_chi[idx] = __nv_bfloat162(h0, h1);
            *(__nv_bfloat162*)&g_clo[idx] =
                __nv_bfloat162(__float2bfloat16(l0), __float2bfloat16(l1));
        }
        {
            float v0 = o[jj][2] * invB, v1 = o[jj][3] * invB;
            __nv_bfloat16 h0, h1; float l0, l1;
            split2(v0, h0, l0); split2(v1, h1, l1);
            size_t idx = (size_t)tokenB * DD + col;
            *(__nv_bfloat162*)&g_chi[idx] = __nv_bfloat162(h0, h1);
            *(__nv_bfloat162*)&g_clo[idx] =
                __nv_bfloat162(__float2bfloat16(l0), __float2bfloat16(l1));
        }
    }
}

// ---------------------------------------------------------------------------
extern "C" void kernel_launch(void* const* d_in, const int* in_sizes, int n_in,
                              void* d_out, int out_size)
{
    const float* X  = (const float*)d_in[0];
    const float* Wq = (const float*)d_in[1];
    const float* bq = (const float*)d_in[2];
    const float* Wk = (const float*)d_in[3];
    const float* bk = (const float*)d_in[4];
    const float* Wv = (const float*)d_in[5];
    const float* bv = (const float*)d_in[6];
    const float* Wo = (const float*)d_in[7];
    const float* bo = (const float*)d_in[8];
    float* out = (float*)d_out;

    cudaFuncSetAttribute(qkv_mma_kernel,
                         cudaFuncAttributeMaxDynamicSharedMemorySize, GSM_BYTES);
    cudaFuncSetAttribute(out_mma_kernel,
                         cudaFuncAttributeMaxDynamicSharedMemorySize, GSM_BYTES);
    cudaFuncSetAttribute(attn_mma_kernel,
                         cudaFuncAttributeMaxDynamicSharedMemorySize, ATTN_SM_BYTES);

    conv_x_kernel<<<2048, 256>>>((const float4*)X);
    conv_w_kernel<<<dim3(16, 16, 3), 256>>>(Wq, Wk, Wv);
    conv_wo_kernel<<<dim3(16, 16), 256>>>(Wo);
    qkv_mma_kernel<<<dim3(32, 8, 3), 256, GSM_BYTES>>>(bq, bk, bv);
    attn_mma_kernel<<<dim3(16, 32), 256, ATTN_SM_BYTES>>>();
    out_mma_kernel<<<dim3(32, 8), 256, GSM_BYTES>>>(bo, out);
}

// round 7
// speedup vs baseline: 2.4985x; 1.0646x over previous
#include <cuda_runtime.h>
#include <cuda_bf16.h>
#include <cstdint>

#define BB 2
#define SS 2048
#define DD 1024
#define HH 16
#define DKH 64
#define BHH (BB*HH)

// ---------------------------------------------------------------------------
// Scratch (allocation-free rule: __device__ globals) — all bf16 hi/lo pairs
// ---------------------------------------------------------------------------
__device__ __nv_bfloat16 g_xhi[BB * SS * DD];
__device__ __nv_bfloat16 g_xlo[BB * SS * DD];
__device__ __nv_bfloat16 g_whi[3 * HH * DKH * DD];   // [(proj*16+h)*64+n][k]
__device__ __nv_bfloat16 g_wlo[3 * HH * DKH * DD];
__device__ __nv_bfloat16 g_qhi[BHH * SS * DKH];      // [bh][s][64] (x 1/8)
__device__ __nv_bfloat16 g_qlo[BHH * SS * DKH];
__device__ __nv_bfloat16 g_khi[BHH * SS * DKH];
__device__ __nv_bfloat16 g_klo[BHH * SS * DKH];
__device__ __nv_bfloat16 g_vhi[BHH * SS * DKH];
__device__ __nv_bfloat16 g_vlo[BHH * SS * DKH];
__device__ __nv_bfloat16 g_chi[BB * SS * HH * DKH];  // ctx [token][1024]
__device__ __nv_bfloat16 g_clo[BB * SS * HH * DKH];
__device__ __nv_bfloat16 g_wohi[DD * DD];            // Wo^T [n][k]
__device__ __nv_bfloat16 g_wolo[DD * DD];

// ---------------------------------------------------------------------------
// Helpers
// ---------------------------------------------------------------------------
__device__ __forceinline__ uint32_t smem_to_u32(const void* p) {
    uint32_t a;
    asm("{ .reg .u64 t; cvta.to.shared.u64 t, %1; cvt.u32.u64 %0, t; }"
        : "=r"(a) : "l"(p));
    return a;
}
__device__ __forceinline__ void ldsm_x4(uint32_t addr, uint32_t* r) {
    asm volatile("ldmatrix.sync.aligned.m8n8.x4.shared.b16 {%0,%1,%2,%3}, [%4];"
        : "=r"(r[0]), "=r"(r[1]), "=r"(r[2]), "=r"(r[3]) : "r"(addr));
}
__device__ __forceinline__ void ldsm_x4_t(uint32_t addr, uint32_t* r) {
    asm volatile("ldmatrix.sync.aligned.m8n8.x4.trans.shared.b16 {%0,%1,%2,%3}, [%4];"
        : "=r"(r[0]), "=r"(r[1]), "=r"(r[2]), "=r"(r[3]) : "r"(addr));
}
__device__ __forceinline__ void mma_bf16(float* d, const uint32_t* a,
                                         uint32_t b0, uint32_t b1) {
    asm volatile(
        "mma.sync.aligned.m16n8k16.row.col.f32.bf16.bf16.f32 "
        "{%0,%1,%2,%3}, {%4,%5,%6,%7}, {%8,%9}, {%0,%1,%2,%3};"
        : "+f"(d[0]), "+f"(d[1]), "+f"(d[2]), "+f"(d[3])
        : "r"(a[0]), "r"(a[1]), "r"(a[2]), "r"(a[3]), "r"(b0), "r"(b1));
}
__device__ __forceinline__ uint32_t pkbf(float lo, float hi) {
    uint32_t r;
    asm("cvt.rn.bf16x2.f32 %0, %1, %2;" : "=r"(r) : "f"(hi), "f"(lo));
    return r;
}
__device__ __forceinline__ void split2(float v, __nv_bfloat16& h, float& l) {
    h = __float2bfloat16(v);
    l = v - __bfloat162float(h);
}
__device__ __forceinline__ void cpasync16(uint32_t dst, const void* src) {
    asm volatile("cp.async.cg.shared.global [%0], [%1], 16;"
                 :: "r"(dst), "l"(src));
}
#define CP_COMMIT() asm volatile("cp.async.commit_group;" ::: "memory")
#define CP_WAIT1()  asm volatile("cp.async.wait_group 1;" ::: "memory")
#define CP_WAIT0()  asm volatile("cp.async.wait_group 0;" ::: "memory")

// ---------------------------------------------------------------------------
// Prep A: split X into bf16 hi/lo.
// ---------------------------------------------------------------------------
__global__ __launch_bounds__(256) void conv_x_kernel(const float4* __restrict__ X4)
{
    int i0 = blockIdx.x * 256 + threadIdx.x;
    #pragma unroll
    for (int l = 0; l < 2; l++) {
        int i = i0 + l * 524288;
        float4 v = X4[i];
        float vv[4] = {v.x, v.y, v.z, v.w};
        union { float2 f; __nv_bfloat16 h[4]; } hi, lo;
        #pragma unroll
        for (int j = 0; j < 4; j++) {
            float lw; split2(vv[j], hi.h[j], lw);
            lo.h[j] = __float2bfloat16(lw);
        }
        ((float2*)g_xhi)[i] = hi.f;
        ((float2*)g_xlo)[i] = lo.f;
    }
}

// ---------------------------------------------------------------------------
// Prep B: transpose + split Wq/Wk/Wv.
// ---------------------------------------------------------------------------
__global__ __launch_bounds__(256) void conv_w_kernel(
    const float* __restrict__ Wq, const float* __restrict__ Wk,
    const float* __restrict__ Wv)
{
    __shared__ float ts[64][65];
    const int k0   = blockIdx.x * 64;
    const int h    = blockIdx.y;
    const int proj = blockIdx.z;
    const float* W = (proj == 0) ? Wq : (proj == 1) ? Wk : Wv;
    W += (size_t)h * DD * DKH;

    const int tid = threadIdx.x;
    #pragma unroll
    for (int l = 0; l < 4; l++) {
        int idx = tid + l * 256;
        int r = idx >> 4, c4 = idx & 15;
        float4 v = *(const float4*)&W[(size_t)(k0 + r) * DKH + c4 * 4];
        ts[r][c4 * 4 + 0] = v.x;
        ts[r][c4 * 4 + 1] = v.y;
        ts[r][c4 * 4 + 2] = v.z;
        ts[r][c4 * 4 + 3] = v.w;
    }
    __syncthreads();
    #pragma unroll
    for (int l = 0; l < 4; l++) {
        int idx = tid + l * 256;
        int nr = idx >> 4, kc = idx & 15;
        size_t orow = ((size_t)(proj * HH + h) * DKH + nr) * DD + k0 + kc * 4;
        #pragma unroll
        for (int j = 0; j < 4; j++) {
            float v = ts[kc * 4 + j][nr];
            __nv_bfloat16 hb; float lw; split2(v, hb, lw);
            g_whi[orow + j] = hb;
            g_wlo[orow + j] = __float2bfloat16(lw);
        }
    }
}

// ---------------------------------------------------------------------------
// Prep C: transpose + split Wo.
// ---------------------------------------------------------------------------
__global__ __launch_bounds__(256) void conv_wo_kernel(const float* __restrict__ Wo)
{
    __shared__ float ts[64][65];
    const int k0 = blockIdx.x * 64;
    const int n0 = blockIdx.y * 64;
    const int tid = threadIdx.x;
    #pragma unroll
    for (int l = 0; l < 4; l++) {
        int idx = tid + l * 256;
        int r = idx >> 4, c4 = idx & 15;
        float4 v = *(const float4*)&Wo[(size_t)(k0 + r) * DD + n0 + c4 * 4];
        ts[r][c4 * 4 + 0] = v.x;
        ts[r][c4 * 4 + 1] = v.y;
        ts[r][c4 * 4 + 2] = v.z;
        ts[r][c4 * 4 + 3] = v.w;
    }
    __syncthreads();
    #pragma unroll
    for (int l = 0; l < 4; l++) {
        int idx = tid + l * 256;
        int nr = idx >> 4, kc = idx & 15;
        size_t orow = (size_t)(n0 + nr) * DD + k0 + kc * 4;
        #pragma unroll
        for (int j = 0; j < 4; j++) {
            float v = ts[kc * 4 + j][nr];
            __nv_bfloat16 hb; float lw; split2(v, hb, lw);
            g_wohi[orow + j] = hb;
            g_wolo[orow + j] = __float2bfloat16(lw);
        }
    }
}

// ---------------------------------------------------------------------------
// Pipelined GEMM plumbing: M128 x N128 CTA, K chunks of 32, 2 stages.
// Warp tile 64x32 (2M x 4N warps) — 12 ldsm per 48 mma per ks.
// ---------------------------------------------------------------------------
#define CROWB 80
#define CTILE (128 * CROWB)       // 10240
#define CSTAGE (4 * CTILE)        // 40960 : AHI | ALO | BHI | BLO
#define GSM_BYTES (2 * CSTAGE)    // 81920

__device__ __forceinline__ void load_stage_g(
    uint32_t sm,
    const __nv_bfloat16* __restrict__ Ahi, const __nv_bfloat16* __restrict__ Alo,
    const __nv_bfloat16* __restrict__ Bhi, const __nv_bfloat16* __restrict__ Blo,
    int k0, int tid)
{
    #pragma unroll
    for (int l = 0; l < 2; l++) {
        int idx = tid + l * 256;
        int r = idx >> 2, c = idx & 3;
        uint32_t dof = (uint32_t)(r * CROWB + c * 16);
        size_t   sof = ((size_t)r * DD + k0) * 2 + c * 16;
        cpasync16(sm + 0 * CTILE + dof, (const char*)Ahi + sof);
        cpasync16(sm + 1 * CTILE + dof, (const char*)Alo + sof);
        cpasync16(sm + 2 * CTILE + dof, (const char*)Bhi + sof);
        cpasync16(sm + 3 * CTILE + dof, (const char*)Blo + sof);
    }
}

__device__ __forceinline__ void gemm_body(
    uint32_t smem_base, uint32_t a_lane, uint32_t b_lane,
    const __nv_bfloat16* Ahi, const __nv_bfloat16* Alo,
    const __nv_bfloat16* Bhi, const __nv_bfloat16* Blo,
    int tid, float acc[4][4][4])
{
    load_stage_g(smem_base, Ahi, Alo, Bhi, Blo, 0, tid);
    CP_COMMIT();
    load_stage_g(smem_base + CSTAGE, Ahi, Alo, Bhi, Blo, 32, tid);
    CP_COMMIT();

    for (int ch = 0; ch < 32; ch++) {
        if (ch >= 30) { CP_WAIT0(); } else { CP_WAIT1(); }
        __syncthreads();
        const uint32_t st = smem_base + (uint32_t)(ch & 1) * CSTAGE;

        #pragma unroll
        for (int ks = 0; ks < 2; ks++) {
            const uint32_t koff = ks * 32;
            uint32_t ahi[4][4], alo[4][4];
            #pragma unroll
            for (int am = 0; am < 4; am++) {
                ldsm_x4(st + 0 * CTILE + a_lane + am * 16 * CROWB + koff, ahi[am]);
                ldsm_x4(st + 1 * CTILE + a_lane + am * 16 * CROWB + koff, alo[am]);
            }
            uint32_t bhi[2][4], blo[2][4];
            #pragma unroll
            for (int bn = 0; bn < 2; bn++) {
                ldsm_x4(st + 2 * CTILE + b_lane + bn * 16 * CROWB + koff, bhi[bn]);
                ldsm_x4(st + 3 * CTILE + b_lane + bn * 16 * CROWB + koff, blo[bn]);
            }
            #pragma unroll
            for (int am = 0; am < 4; am++) {
                #pragma unroll
                for (int bn = 0; bn < 2; bn++) {
                    mma_bf16(acc[am][2*bn],   ahi[am], bhi[bn][0], bhi[bn][2]);
                    mma_bf16(acc[am][2*bn+1], ahi[am], bhi[bn][1], bhi[bn][3]);
                    mma_bf16(acc[am][2*bn],   ahi[am], blo[bn][0], blo[bn][2]);
                    mma_bf16(acc[am][2*bn+1], ahi[am], blo[bn][1], blo[bn][3]);
                    mma_bf16(acc[am][2*bn],   alo[am], bhi[bn][0], bhi[bn][2]);
                    mma_bf16(acc[am][2*bn+1], alo[am], bhi[bn][1], bhi[bn][3]);
                }
            }
        }
        __syncthreads();
        if (ch + 2 < 32) {
            load_stage_g(smem_base + (uint32_t)(ch & 1) * CSTAGE,
                         Ahi, Alo, Bhi, Blo, (ch + 2) * 32, tid);
            CP_COMMIT();
        }
    }
}

// ---------------------------------------------------------------------------
// QKV GEMM: writes Q/K/V as bf16 hi/lo (Q scaled by 1/8).
// ---------------------------------------------------------------------------
__global__ __launch_bounds__(256, 1) void qkv_mma_kernel(
    const float* __restrict__ bq, const float* __restrict__ bk,
    const float* __restrict__ bv)
{
    extern __shared__ char smem[];
    const uint32_t smem_base = smem_to_u32(smem);
    const int tid  = threadIdx.x;
    const int lane = tid & 31;
    const int wid  = tid >> 5;
    const int warpM = wid & 1;          // 2 groups x 64 rows
    const int warpN = wid >> 1;         // 4 groups x 32 cols

    const int m0   = blockIdx.x * 128;
    const int hg   = blockIdx.y;
    const int proj = blockIdx.z;

    const float* bias = (proj == 0) ? bq : (proj == 1) ? bk : bv;
    __nv_bfloat16* ohi = (proj == 0) ? g_qhi : (proj == 1) ? g_khi : g_vhi;
    __nv_bfloat16* olo = (proj == 0) ? g_qlo : (proj == 1) ? g_klo : g_vlo;
    const float scale = (proj == 0) ? 0.125f : 1.0f;

    const size_t brow = ((size_t)proj * HH * DKH + (size_t)hg * 128) * DD;

    float acc[4][4][4] = {};

    const int lrow  = lane & 15;
    const int lhalf = lane >> 4;
    const uint32_t a_lane = (uint32_t)((warpM * 64 + lrow) * CROWB + lhalf * 16);
    const uint32_t b_lane = (uint32_t)((warpN * 32 + lrow) * CROWB + lhalf * 16);

    gemm_body(smem_base, a_lane, b_lane,
              g_xhi + (size_t)m0 * DD, g_xlo + (size_t)m0 * DD,
              g_whi + brow, g_wlo + brow, tid, acc);

    #pragma unroll
    for (int am = 0; am < 4; am++) {
        #pragma unroll
        for (int rh = 0; rh < 2; rh++) {
            const int token = m0 + warpM * 64 + am * 16 + rh * 8 + (lane >> 2);
            const int b_ = token >> 11;
            const int s_ = token & (SS - 1);
            #pragma unroll
            for (int na = 0; na < 4; na++) {
                const int ng = hg * 128 + warpN * 32 + na * 8 + (lane & 3) * 2;
                const int h  = ng >> 6;
                const int dk = ng & 63;
                float v0 = (acc[am][na][rh*2+0] + __ldg(&bias[h*DKH + dk]))   * scale;
                float v1 = (acc[am][na][rh*2+1] + __ldg(&bias[h*DKH + dk+1])) * scale;
                __nv_bfloat16 h0, h1; float l0, l1;
                split2(v0, h0, l0); split2(v1, h1, l1);
                size_t idx = ((size_t)(b_ * HH + h) * SS + s_) * DKH + dk;
                *(__nv_bfloat162*)&ohi[idx] = __nv_bfloat162(h0, h1);
                *(__nv_bfloat162*)&olo[idx] =
                    __nv_bfloat162(__float2bfloat16(l0), __float2bfloat16(l1));
            }
        }
    }
}

// ---------------------------------------------------------------------------
// Output projection: out = ctx @ Wo + bo (fp32 out).
// ---------------------------------------------------------------------------
__global__ __launch_bounds__(256, 1) void out_mma_kernel(
    const float* __restrict__ bo, float* __restrict__ out)
{
    extern __shared__ char smem[];
    const uint32_t smem_base = smem_to_u32(smem);
    const int tid  = threadIdx.x;
    const int lane = tid & 31;
    const int wid  = tid >> 5;
    const int warpM = wid & 1;
    const int warpN = wid >> 1;

    const int m0 = blockIdx.x * 128;
    const int n0 = blockIdx.y * 128;

    float acc[4][4][4] = {};

    const int lrow  = lane & 15;
    const int lhalf = lane >> 4;
    const uint32_t a_lane = (uint32_t)((warpM * 64 + lrow) * CROWB + lhalf * 16);
    const uint32_t b_lane = (uint32_t)((warpN * 32 + lrow) * CROWB + lhalf * 16);

    gemm_body(smem_base, a_lane, b_lane,
              g_chi + (size_t)m0 * DD, g_clo + (size_t)m0 * DD,
              g_wohi + (size_t)n0 * DD, g_wolo + (size_t)n0 * DD, tid, acc);

    #pragma unroll
    for (int am = 0; am < 4; am++) {
        #pragma unroll
        for (int rh = 0; rh < 2; rh++) {
            const int token = m0 + warpM * 64 + am * 16 + rh * 8 + (lane >> 2);
            #pragma unroll
            for (int na = 0; na < 4; na++) {
                const int n = n0 + warpN * 32 + na * 8 + (lane & 3) * 2;
                float2 o;
                o.x = acc[am][na][rh*2+0] + __ldg(&bo[n]);
                o.y = acc[am][na][rh*2+1] + __ldg(&bo[n+1]);
                *(float2*)&out[(size_t)token * DD + n] = o;
            }
        }
    }
}

// ---------------------------------------------------------------------------
// Flash attention, pipelined, 32 q-rows per warp (q-tile 256).
// grid (8 q-tiles, 32 bh); block 256.
// ---------------------------------------------------------------------------
#define AROWB 144                    // 72 bf16 per row
#define ATILE (64 * AROWB)           // 9216
#define AST (4 * ATILE)              // 36864 : KHI | KLO | VHI | VLO
#define ATTN_SM_BYTES (2 * AST)      // 73728

__device__ __forceinline__ void attn_load_stage(
    uint32_t sm, size_t key0, int tid)
{
    #pragma unroll
    for (int l = 0; l < 2; l++) {
        int idx = tid + l * 256;
        int r = idx >> 3, c = idx & 7;
        uint32_t dof = (uint32_t)(r * AROWB + c * 16);
        size_t   sof = ((size_t)r * DKH) * 2 + c * 16;
        cpasync16(sm + 0 * ATILE + dof, (const char*)(g_khi + key0) + sof);
        cpasync16(sm + 1 * ATILE + dof, (const char*)(g_klo + key0) + sof);
        cpasync16(sm + 2 * ATILE + dof, (const char*)(g_vhi + key0) + sof);
        cpasync16(sm + 3 * ATILE + dof, (const char*)(g_vlo + key0) + sof);
    }
}

__global__ __launch_bounds__(256, 1) void attn_mma_kernel()
{
    extern __shared__ char smem[];
    const uint32_t smem_base = smem_to_u32(smem);
    const int tid  = threadIdx.x;
    const int lane = tid & 31;
    const int w    = tid >> 5;          // warp 0..7 -> q rows w*32..w*32+31

    const int bh = blockIdx.y;
    const int q0 = blockIdx.x * 256;
    const size_t base = (size_t)bh * SS * DKH;

    const int lrow  = lane & 15;
    const int lhalf = lane >> 4;

    // ---- stage Q (256 x 64): hi -> stage0 region, lo -> stage1 region ----
    {
        const __nv_bfloat16* Qh = g_qhi + base + (size_t)q0 * DKH;
        const __nv_bfloat16* Ql = g_qlo + base + (size_t)q0 * DKH;
        #pragma unroll
        for (int l = 0; l < 8; l++) {
            int idx = tid + l * 256;
            int r = idx >> 3, c = idx & 7;
            uint32_t dof = (uint32_t)(r * AROWB + c * 16);
            size_t   sof = ((size_t)r * DKH) * 2 + c * 16;
            cpasync16(smem_base + dof,       (const char*)Qh + sof);
            cpasync16(smem_base + AST + dof, (const char*)Ql + sof);
        }
        CP_COMMIT();
        CP_WAIT0();
    }
    __syncthreads();

    uint32_t qhi[2][4][4], qlo[2][4][4];   // [am][ks][regs]
    #pragma unroll
    for (int am = 0; am < 2; am++) {
        const uint32_t qa = smem_base +
            (uint32_t)((w * 32 + am * 16 + lrow) * AROWB + lhalf * 16);
        #pragma unroll
        for (int ks = 0; ks < 4; ks++) {
            ldsm_x4(qa + ks * 32, qhi[am][ks]);
            ldsm_x4(qa + AST + ks * 32, qlo[am][ks]);
        }
    }
    __syncthreads();     // all warps done reading Q
    attn_load_stage(smem_base, base, tid);
    CP_COMMIT();
    attn_load_stage(smem_base + AST, base + (size_t)64 * DKH, tid);
    CP_COMMIT();

    float o[2][8][4] = {};
    float m[2][2], l[2][2];
    #pragma unroll
    for (int am = 0; am < 2; am++) {
        m[am][0] = -1e30f; m[am][1] = -1e30f;
        l[am][0] = 0.0f;   l[am][1] = 0.0f;
    }

    const uint32_t lane_off = (uint32_t)(lrow * AROWB + lhalf * 16);

    for (int ch = 0; ch < 32; ch++) {
        if (ch >= 30) { CP_WAIT0(); } else { CP_WAIT1(); }
        __syncthreads();
        const uint32_t st = smem_base + (uint32_t)(ch & 1) * AST;
        const uint32_t kb = st + lane_off;

        // ---- S = Q K^T : 32 x 64 per warp, 3-pass ----
        float s[2][8][4] = {};
        #pragma unroll
        for (int ks = 0; ks < 4; ks++) {
            const uint32_t koff = ks * 32;
            #pragma unroll
            for (int bn = 0; bn < 4; bn++) {
                uint32_t kh[4], kl[4];
                ldsm_x4(kb + 0 * ATILE + bn * 16 * AROWB + koff, kh);
                ldsm_x4(kb + 1 * ATILE + bn * 16 * AROWB + koff, kl);
                #pragma unroll
                for (int am = 0; am < 2; am++) {
                    mma_bf16(s[am][2*bn],   qhi[am][ks], kh[0], kh[2]);
                    mma_bf16(s[am][2*bn+1], qhi[am][ks], kh[1], kh[3]);
                    mma_bf16(s[am][2*bn],   qhi[am][ks], kl[0], kl[2]);
                    mma_bf16(s[am][2*bn+1], qhi[am][ks], kl[1], kl[3]);
                    mma_bf16(s[am][2*bn],   qlo[am][ks], kh[0], kh[2]);
                    mma_bf16(s[am][2*bn+1], qlo[am][ks], kh[1], kh[3]);
                }
            }
        }

        // ---- online softmax per am group ----
        #pragma unroll
        for (int am = 0; am < 2; am++) {
            float mxA = -1e30f, mxB = -1e30f;
            #pragma unroll
            for (int j = 0; j < 8; j++) {
                mxA = fmaxf(mxA, fmaxf(s[am][j][0], s[am][j][1]));
                mxB = fmaxf(mxB, fmaxf(s[am][j][2], s[am][j][3]));
            }
            #pragma unroll
            for (int msk = 1; msk < 4; msk <<= 1) {
                mxA = fmaxf(mxA, __shfl_xor_sync(0xffffffffu, mxA, msk));
                mxB = fmaxf(mxB, __shfl_xor_sync(0xffffffffu, mxB, msk));
            }
            const float mnA = fmaxf(m[am][0], mxA);
            const float mnB = fmaxf(m[am][1], mxB);
            const float fA = __expf(m[am][0] - mnA);
            const float fB = __expf(m[am][1] - mnB);
            m[am][0] = mnA; m[am][1] = mnB;
            float rsA = 0.0f, rsB = 0.0f;
            #pragma unroll
            for (int j = 0; j < 8; j++) {
                s[am][j][0] = __expf(s[am][j][0] - mnA); rsA += s[am][j][0];
                s[am][j][1] = __expf(s[am][j][1] - mnA); rsA += s[am][j][1];
                s[am][j][2] = __expf(s[am][j][2] - mnB); rsB += s[am][j][2];
                s[am][j][3] = __expf(s[am][j][3] - mnB); rsB += s[am][j][3];
            }
            #pragma unroll
            for (int msk = 1; msk < 4; msk <<= 1) {
                rsA += __shfl_xor_sync(0xffffffffu, rsA, msk);
                rsB += __shfl_xor_sync(0xffffffffu, rsB, msk);
            }
            l[am][0] = l[am][0] * fA + rsA;
            l[am][1] = l[am][1] * fB + rsB;
            #pragma unroll
            for (int j = 0; j < 8; j++) {
                o[am][j][0] *= fA; o[am][j][1] *= fA;
                o[am][j][2] *= fB; o[am][j][3] *= fB;
            }
        }

        // ---- O += P V ----
        #pragma unroll
        for (int j = 0; j < 4; j++) {
            uint32_t ph[2][4], pl[2][4];
            #pragma unroll
            for (int am = 0; am < 2; am++) {
                __nv_bfloat16 hb[8]; float lw[8];
                split2(s[am][2*j][0],   hb[0], lw[0]);
                split2(s[am][2*j][1],   hb[1], lw[1]);
                split2(s[am][2*j][2],   hb[2], lw[2]);
                split2(s[am][2*j][3],   hb[3], lw[3]);
                split2(s[am][2*j+1][0], hb[4], lw[4]);
                split2(s[am][2*j+1][1], hb[5], lw[5]);
                split2(s[am][2*j+1][2], hb[6], lw[6]);
                split2(s[am][2*j+1][3], hb[7], lw[7]);
                union { __nv_bfloat162 b2; uint32_t u; } t;
                t.b2 = __nv_bfloat162(hb[0], hb[1]); ph[am][0] = t.u;
                t.b2 = __nv_bfloat162(hb[2], hb[3]); ph[am][1] = t.u;
                t.b2 = __nv_bfloat162(hb[4], hb[5]); ph[am][2] = t.u;
                t.b2 = __nv_bfloat162(hb[6], hb[7]); ph[am][3] = t.u;
                pl[am][0] = pkbf(lw[0], lw[1]);
                pl[am][1] = pkbf(lw[2], lw[3]);
                pl[am][2] = pkbf(lw[4], lw[5]);
                pl[am][3] = pkbf(lw[6], lw[7]);
            }
            const uint32_t vrow = st + (uint32_t)((j * 16 + lrow) * AROWB + lhalf * 16);
            #pragma unroll
            for (int dvp = 0; dvp < 4; dvp++) {
                uint32_t vh[4], vl[4];
                ldsm_x4_t(vrow + 2 * ATILE + dvp * 32, vh);
                ldsm_x4_t(vrow + 3 * ATILE + dvp * 32, vl);
                #pragma unroll
                for (int am = 0; am < 2; am++) {
                    mma_bf16(o[am][2*dvp],   ph[am], vh[0], vh[1]);
                    mma_bf16(o[am][2*dvp+1], ph[am], vh[2], vh[3]);
                    mma_bf16(o[am][2*dvp],   ph[am], vl[0], vl[1]);
                    mma_bf16(o[am][2*dvp+1], ph[am], vl[2], vl[3]);
                    mma_bf16(o[am][2*dvp],   pl[am], vh[0], vh[1]);
                    mma_bf16(o[am][2*dvp+1], pl[am], vh[2], vh[3]);
                }
            }
        }
        __syncthreads();
        if (ch + 2 < 32) {
            attn_load_stage(smem_base + (uint32_t)(ch & 1) * AST,
                            base + (size_t)((ch + 2) * 64) * DKH, tid);
            CP_COMMIT();
        }
    }

    // ---- epilogue: normalize, split hi/lo, write ctx [token][1024] ----
    const int b_ = bh / HH;
    const int h_ = bh % HH;
    #pragma unroll
    for (int am = 0; am < 2; am++) {
        const float invA = 1.0f / l[am][0];
        const float invB = 1.0f / l[am][1];
        const int rA = q0 + w * 32 + am * 16 + (lane >> 2);
        const int tokenA = b_ * SS + rA;
        const int tokenB = tokenA + 8;
        #pragma unroll
        for (int jj = 0; jj < 8; jj++) {
            const int col = h_ * DKH + jj * 8 + (lane & 3) * 2;
            {
                float v0 = o[am][jj][0] * invA, v1 = o[am][jj][1] * invA;
                __nv_bfloat16 h0, h1; float l0, l1;
                split2(v0, h0, l0); split2(v1, h1, l1);
                size_t idx = (size_t)tokenA * DD + col;
                *(__nv_bfloat162*)&g_chi[idx] = __nv_bfloat162(h0, h1);
                *(__nv_bfloat162*)&g_clo[idx] =
                    __nv_bfloat162(__float2bfloat16(l0), __float2bfloat16(l1));
            }
            {
                float v0 = o[am][jj][2] * invB, v1 = o[am][jj][3] * invB;
                __nv_bfloat16 h0, h1; float l0, l1;
                split2(v0, h0, l0); split2(v1, h1, l1);
                size_t idx = (size_t)tokenB * DD + col;
                *(__nv_bfloat162*)&g_chi[idx] = __nv_bfloat162(h0, h1);
                *(__nv_bfloat162*)&g_clo[idx] =
                    __nv_bfloat162(__float2bfloat16(l0), __float2bfloat16(l1));
            }
        }
    }
}

// ---------------------------------------------------------------------------
extern "C" void kernel_launch(void* const* d_in, const int* in_sizes, int n_in,
                              void* d_out, int out_size)
{
    const float* X  = (const float*)d_in[0];
    const float* Wq = (const float*)d_in[1];
    const float* bq = (const float*)d_in[2];
    const float* Wk = (const float*)d_in[3];
    const float* bk = (const float*)d_in[4];
    const float* Wv = (const float*)d_in[5];
    const float* bv = (const float*)d_in[6];
    const float* Wo = (const float*)d_in[7];
    const float* bo = (const float*)d_in[8];
    float* out = (float*)d_out;

    cudaFuncSetAttribute(qkv_mma_kernel,
                         cudaFuncAttributeMaxDynamicSharedMemorySize, GSM_BYTES);
    cudaFuncSetAttribute(out_mma_kernel,
                         cudaFuncAttributeMaxDynamicSharedMemorySize, GSM_BYTES);
    cudaFuncSetAttribute(attn_mma_kernel,
                         cudaFuncAttributeMaxDynamicSharedMemorySize, ATTN_SM_BYTES);

    conv_x_kernel<<<2048, 256>>>((const float4*)X);
    conv_w_kernel<<<dim3(16, 16, 3), 256>>>(Wq, Wk, Wv);
    conv_wo_kernel<<<dim3(16, 16), 256>>>(Wo);
    qkv_mma_kernel<<<dim3(32, 8, 3), 256, GSM_BYTES>>>(bq, bk, bv);
    attn_mma_kernel<<<dim3(8, 32), 256, ATTN_SM_BYTES>>>();
    out_mma_kernel<<<dim3(32, 8), 256, GSM_BYTES>>>(bo, out);
}

// round 8
// speedup vs baseline: 2.6139x; 1.0462x over previous
#include <cuda_runtime.h>
#include <cuda_bf16.h>
#include <cstdint>

#define BB 2
#define SS 2048
#define DD 1024
#define HH 16
#define DKH 64
#define BHH (BB*HH)

// ---------------------------------------------------------------------------
// Scratch (allocation-free rule: __device__ globals) — all bf16 hi/lo pairs
// ---------------------------------------------------------------------------
__device__ __nv_bfloat16 g_xhi[BB * SS * DD];
__device__ __nv_bfloat16 g_xlo[BB * SS * DD];
__device__ __nv_bfloat16 g_whi[3 * HH * DKH * DD];   // [(proj*16+h)*64+n][k]
__device__ __nv_bfloat16 g_wlo[3 * HH * DKH * DD];
__device__ __nv_bfloat16 g_qhi[BHH * SS * DKH];      // [bh][s][64] (x 1/8)
__device__ __nv_bfloat16 g_qlo[BHH * SS * DKH];
__device__ __nv_bfloat16 g_khi[BHH * SS * DKH];
__device__ __nv_bfloat16 g_klo[BHH * SS * DKH];
__device__ __nv_bfloat16 g_vhi[BHH * SS * DKH];
__device__ __nv_bfloat16 g_vlo[BHH * SS * DKH];
__device__ __nv_bfloat16 g_chi[BB * SS * HH * DKH];  // ctx [token][1024]
__device__ __nv_bfloat16 g_clo[BB * SS * HH * DKH];
__device__ __nv_bfloat16 g_wohi[DD * DD];            // Wo^T [n][k]
__device__ __nv_bfloat16 g_wolo[DD * DD];

// ---------------------------------------------------------------------------
// Helpers
// ---------------------------------------------------------------------------
__device__ __forceinline__ uint32_t smem_to_u32(const void* p) {
    uint32_t a;
    asm("{ .reg .u64 t; cvta.to.shared.u64 t, %1; cvt.u32.u64 %0, t; }"
        : "=r"(a) : "l"(p));
    return a;
}
__device__ __forceinline__ void ldsm_x4(uint32_t addr, uint32_t* r) {
    asm volatile("ldmatrix.sync.aligned.m8n8.x4.shared.b16 {%0,%1,%2,%3}, [%4];"
        : "=r"(r[0]), "=r"(r[1]), "=r"(r[2]), "=r"(r[3]) : "r"(addr));
}
__device__ __forceinline__ void ldsm_x4_t(uint32_t addr, uint32_t* r) {
    asm volatile("ldmatrix.sync.aligned.m8n8.x4.trans.shared.b16 {%0,%1,%2,%3}, [%4];"
        : "=r"(r[0]), "=r"(r[1]), "=r"(r[2]), "=r"(r[3]) : "r"(addr));
}
__device__ __forceinline__ void mma_bf16(float* d, const uint32_t* a,
                                         uint32_t b0, uint32_t b1) {
    asm volatile(
        "mma.sync.aligned.m16n8k16.row.col.f32.bf16.bf16.f32 "
        "{%0,%1,%2,%3}, {%4,%5,%6,%7}, {%8,%9}, {%0,%1,%2,%3};"
        : "+f"(d[0]), "+f"(d[1]), "+f"(d[2]), "+f"(d[3])
        : "r"(a[0]), "r"(a[1]), "r"(a[2]), "r"(a[3]), "r"(b0), "r"(b1));
}
__device__ __forceinline__ uint32_t pkbf(float lo, float hi) {
    uint32_t r;
    asm("cvt.rn.bf16x2.f32 %0, %1, %2;" : "=r"(r) : "f"(hi), "f"(lo));
    return r;
}
__device__ __forceinline__ void split2(float v, __nv_bfloat16& h, float& l) {
    h = __float2bfloat16(v);
    l = v - __bfloat162float(h);
}
__device__ __forceinline__ void cpasync16(uint32_t dst, const void* src) {
    asm volatile("cp.async.cg.shared.global [%0], [%1], 16;"
                 :: "r"(dst), "l"(src));
}
#define CP_COMMIT() asm volatile("cp.async.commit_group;" ::: "memory")
#define CP_WAIT1()  asm volatile("cp.async.wait_group 1;" ::: "memory")
#define CP_WAIT0()  asm volatile("cp.async.wait_group 0;" ::: "memory")

// ---------------------------------------------------------------------------
// Prep A: split X into bf16 hi/lo.
// ---------------------------------------------------------------------------
__global__ __launch_bounds__(256) void conv_x_kernel(const float4* __restrict__ X4)
{
    int i0 = blockIdx.x * 256 + threadIdx.x;
    #pragma unroll
    for (int l = 0; l < 2; l++) {
        int i = i0 + l * 524288;
        float4 v = X4[i];
        float vv[4] = {v.x, v.y, v.z, v.w};
        union { float2 f; __nv_bfloat16 h[4]; } hi, lo;
        #pragma unroll
        for (int j = 0; j < 4; j++) {
            float lw; split2(vv[j], hi.h[j], lw);
            lo.h[j] = __float2bfloat16(lw);
        }
        ((float2*)g_xhi)[i] = hi.f;
        ((float2*)g_xlo)[i] = lo.f;
    }
}

// ---------------------------------------------------------------------------
// Prep B: transpose + split Wq/Wk/Wv.
// ---------------------------------------------------------------------------
__global__ __launch_bounds__(256) void conv_w_kernel(
    const float* __restrict__ Wq, const float* __restrict__ Wk,
    const float* __restrict__ Wv)
{
    __shared__ float ts[64][65];
    const int k0   = blockIdx.x * 64;
    const int h    = blockIdx.y;
    const int proj = blockIdx.z;
    const float* W = (proj == 0) ? Wq : (proj == 1) ? Wk : Wv;
    W += (size_t)h * DD * DKH;

    const int tid = threadIdx.x;
    #pragma unroll
    for (int l = 0; l < 4; l++) {
        int idx = tid + l * 256;
        int r = idx >> 4, c4 = idx & 15;
        float4 v = *(const float4*)&W[(size_t)(k0 + r) * DKH + c4 * 4];
        ts[r][c4 * 4 + 0] = v.x;
        ts[r][c4 * 4 + 1] = v.y;
        ts[r][c4 * 4 + 2] = v.z;
        ts[r][c4 * 4 + 3] = v.w;
    }
    __syncthreads();
    #pragma unroll
    for (int l = 0; l < 4; l++) {
        int idx = tid + l * 256;
        int nr = idx >> 4, kc = idx & 15;
        size_t orow = ((size_t)(proj * HH + h) * DKH + nr) * DD + k0 + kc * 4;
        #pragma unroll
        for (int j = 0; j < 4; j++) {
            float v = ts[kc * 4 + j][nr];
            __nv_bfloat16 hb; float lw; split2(v, hb, lw);
            g_whi[orow + j] = hb;
            g_wlo[orow + j] = __float2bfloat16(lw);
        }
    }
}

// ---------------------------------------------------------------------------
// Prep C: transpose + split Wo.
// ---------------------------------------------------------------------------
__global__ __launch_bounds__(256) void conv_wo_kernel(const float* __restrict__ Wo)
{
    __shared__ float ts[64][65];
    const int k0 = blockIdx.x * 64;
    const int n0 = blockIdx.y * 64;
    const int tid = threadIdx.x;
    #pragma unroll
    for (int l = 0; l < 4; l++) {
        int idx = tid + l * 256;
        int r = idx >> 4, c4 = idx & 15;
        float4 v = *(const float4*)&Wo[(size_t)(k0 + r) * DD + n0 + c4 * 4];
        ts[r][c4 * 4 + 0] = v.x;
        ts[r][c4 * 4 + 1] = v.y;
        ts[r][c4 * 4 + 2] = v.z;
        ts[r][c4 * 4 + 3] = v.w;
    }
    __syncthreads();
    #pragma unroll
    for (int l = 0; l < 4; l++) {
        int idx = tid + l * 256;
        int nr = idx >> 4, kc = idx & 15;
        size_t orow = (size_t)(n0 + nr) * DD + k0 + kc * 4;
        #pragma unroll
        for (int j = 0; j < 4; j++) {
            float v = ts[kc * 4 + j][nr];
            __nv_bfloat16 hb; float lw; split2(v, hb, lw);
            g_wohi[orow + j] = hb;
            g_wolo[orow + j] = __float2bfloat16(lw);
        }
    }
}

// ---------------------------------------------------------------------------
// Pipelined GEMM plumbing: M128 x N128 CTA, K chunks of 32, 2 stages.
// Warp tile 64x32 (2M x 4N warps). 2 CTAs/SM (regs capped at 128).
// ---------------------------------------------------------------------------
#define CROWB 80
#define CTILE (128 * CROWB)       // 10240
#define CSTAGE (4 * CTILE)        // 40960 : AHI | ALO | BHI | BLO
#define GSM_BYTES (2 * CSTAGE)    // 81920

__device__ __forceinline__ void load_stage_g(
    uint32_t sm,
    const __nv_bfloat16* __restrict__ Ahi, const __nv_bfloat16* __restrict__ Alo,
    const __nv_bfloat16* __restrict__ Bhi, const __nv_bfloat16* __restrict__ Blo,
    int k0, int tid)
{
    #pragma unroll
    for (int l = 0; l < 2; l++) {
        int idx = tid + l * 256;
        int r = idx >> 2, c = idx & 3;
        uint32_t dof = (uint32_t)(r * CROWB + c * 16);
        size_t   sof = ((size_t)r * DD + k0) * 2 + c * 16;
        cpasync16(sm + 0 * CTILE + dof, (const char*)Ahi + sof);
        cpasync16(sm + 1 * CTILE + dof, (const char*)Alo + sof);
        cpasync16(sm + 2 * CTILE + dof, (const char*)Bhi + sof);
        cpasync16(sm + 3 * CTILE + dof, (const char*)Blo + sof);
    }
}

__device__ __forceinline__ void gemm_body(
    uint32_t smem_base, uint32_t a_lane, uint32_t b_lane,
    const __nv_bfloat16* Ahi, const __nv_bfloat16* Alo,
    const __nv_bfloat16* Bhi, const __nv_bfloat16* Blo,
    int tid, float acc[4][4][4])
{
    load_stage_g(smem_base, Ahi, Alo, Bhi, Blo, 0, tid);
    CP_COMMIT();
    load_stage_g(smem_base + CSTAGE, Ahi, Alo, Bhi, Blo, 32, tid);
    CP_COMMIT();

    for (int ch = 0; ch < 32; ch++) {
        if (ch >= 30) { CP_WAIT0(); } else { CP_WAIT1(); }
        __syncthreads();
        const uint32_t st = smem_base + (uint32_t)(ch & 1) * CSTAGE;

        #pragma unroll
        for (int ks = 0; ks < 2; ks++) {
            const uint32_t koff = ks * 32;
            uint32_t ahi[4][4], alo[4][4];
            #pragma unroll
            for (int am = 0; am < 4; am++) {
                ldsm_x4(st + 0 * CTILE + a_lane + am * 16 * CROWB + koff, ahi[am]);
                ldsm_x4(st + 1 * CTILE + a_lane + am * 16 * CROWB + koff, alo[am]);
            }
            uint32_t bhi[2][4], blo[2][4];
            #pragma unroll
            for (int bn = 0; bn < 2; bn++) {
                ldsm_x4(st + 2 * CTILE + b_lane + bn * 16 * CROWB + koff, bhi[bn]);
                ldsm_x4(st + 3 * CTILE + b_lane + bn * 16 * CROWB + koff, blo[bn]);
            }
            #pragma unroll
            for (int am = 0; am < 4; am++) {
                #pragma unroll
                for (int bn = 0; bn < 2; bn++) {
                    mma_bf16(acc[am][2*bn],   ahi[am], bhi[bn][0], bhi[bn][2]);
                    mma_bf16(acc[am][2*bn+1], ahi[am], bhi[bn][1], bhi[bn][3]);
                    mma_bf16(acc[am][2*bn],   ahi[am], blo[bn][0], blo[bn][2]);
                    mma_bf16(acc[am][2*bn+1], ahi[am], blo[bn][1], blo[bn][3]);
                    mma_bf16(acc[am][2*bn],   alo[am], bhi[bn][0], bhi[bn][2]);
                    mma_bf16(acc[am][2*bn+1], alo[am], bhi[bn][1], bhi[bn][3]);
                }
            }
        }
        __syncthreads();
        if (ch + 2 < 32) {
            load_stage_g(smem_base + (uint32_t)(ch & 1) * CSTAGE,
                         Ahi, Alo, Bhi, Blo, (ch + 2) * 32, tid);
            CP_COMMIT();
        }
    }
}

// ---------------------------------------------------------------------------
// QKV GEMM: writes Q/K/V as bf16 hi/lo (Q scaled by 1/8). 2 CTAs/SM.
// ---------------------------------------------------------------------------
__global__ __launch_bounds__(256, 2) void qkv_mma_kernel(
    const float* __restrict__ bq, const float* __restrict__ bk,
    const float* __restrict__ bv)
{
    extern __shared__ char smem[];
    const uint32_t smem_base = smem_to_u32(smem);
    const int tid  = threadIdx.x;
    const int lane = tid & 31;
    const int wid  = tid >> 5;
    const int warpM = wid & 1;          // 2 groups x 64 rows
    const int warpN = wid >> 1;         // 4 groups x 32 cols

    const int m0   = blockIdx.x * 128;
    const int hg   = blockIdx.y;
    const int proj = blockIdx.z;

    const float* bias = (proj == 0) ? bq : (proj == 1) ? bk : bv;
    __nv_bfloat16* ohi = (proj == 0) ? g_qhi : (proj == 1) ? g_khi : g_vhi;
    __nv_bfloat16* olo = (proj == 0) ? g_qlo : (proj == 1) ? g_klo : g_vlo;
    const float scale = (proj == 0) ? 0.125f : 1.0f;

    const size_t brow = ((size_t)proj * HH * DKH + (size_t)hg * 128) * DD;

    float acc[4][4][4] = {};

    const int lrow  = lane & 15;
    const int lhalf = lane >> 4;
    const uint32_t a_lane = (uint32_t)((warpM * 64 + lrow) * CROWB + lhalf * 16);
    const uint32_t b_lane = (uint32_t)((warpN * 32 + lrow) * CROWB + lhalf * 16);

    gemm_body(smem_base, a_lane, b_lane,
              g_xhi + (size_t)m0 * DD, g_xlo + (size_t)m0 * DD,
              g_whi + brow, g_wlo + brow, tid, acc);

    #pragma unroll
    for (int am = 0; am < 4; am++) {
        #pragma unroll
        for (int rh = 0; rh < 2; rh++) {
            const int token = m0 + warpM * 64 + am * 16 + rh * 8 + (lane >> 2);
            const int b_ = token >> 11;
            const int s_ = token & (SS - 1);
            #pragma unroll
            for (int na = 0; na < 4; na++) {
                const int ng = hg * 128 + warpN * 32 + na * 8 + (lane & 3) * 2;
                const int h  = ng >> 6;
                const int dk = ng & 63;
                float v0 = (acc[am][na][rh*2+0] + __ldg(&bias[h*DKH + dk]))   * scale;
                float v1 = (acc[am][na][rh*2+1] + __ldg(&bias[h*DKH + dk+1])) * scale;
                __nv_bfloat16 h0, h1; float l0, l1;
                split2(v0, h0, l0); split2(v1, h1, l1);
                size_t idx = ((size_t)(b_ * HH + h) * SS + s_) * DKH + dk;
                *(__nv_bfloat162*)&ohi[idx] = __nv_bfloat162(h0, h1);
                *(__nv_bfloat162*)&olo[idx] =
                    __nv_bfloat162(__float2bfloat16(l0), __float2bfloat16(l1));
            }
        }
    }
}

// ---------------------------------------------------------------------------
// Output projection: out = ctx @ Wo + bo (fp32 out). 2 CTAs/SM.
// ---------------------------------------------------------------------------
__global__ __launch_bounds__(256, 2) void out_mma_kernel(
    const float* __restrict__ bo, float* __restrict__ out)
{
    extern __shared__ char smem[];
    const uint32_t smem_base = smem_to_u32(smem);
    const int tid  = threadIdx.x;
    const int lane = tid & 31;
    const int wid  = tid >> 5;
    const int warpM = wid & 1;
    const int warpN = wid >> 1;

    const int m0 = blockIdx.x * 128;
    const int n0 = blockIdx.y * 128;

    float acc[4][4][4] = {};

    const int lrow  = lane & 15;
    const int lhalf = lane >> 4;
    const uint32_t a_lane = (uint32_t)((warpM * 64 + lrow) * CROWB + lhalf * 16);
    const uint32_t b_lane = (uint32_t)((warpN * 32 + lrow) * CROWB + lhalf * 16);

    gemm_body(smem_base, a_lane, b_lane,
              g_chi + (size_t)m0 * DD, g_clo + (size_t)m0 * DD,
              g_wohi + (size_t)n0 * DD, g_wolo + (size_t)n0 * DD, tid, acc);

    #pragma unroll
    for (int am = 0; am < 4; am++) {
        #pragma unroll
        for (int rh = 0; rh < 2; rh++) {
            const int token = m0 + warpM * 64 + am * 16 + rh * 8 + (lane >> 2);
            #pragma unroll
            for (int na = 0; na < 4; na++) {
                const int n = n0 + warpN * 32 + na * 8 + (lane & 3) * 2;
                float2 o;
                o.x = acc[am][na][rh*2+0] + __ldg(&bo[n]);
                o.y = acc[am][na][rh*2+1] + __ldg(&bo[n+1]);
                *(float2*)&out[(size_t)token * DD + n] = o;
            }
        }
    }
}

// ---------------------------------------------------------------------------
// Flash attention, pipelined, 32 q-rows per warp (q-tile 256).
// grid (8 q-tiles, 32 bh); block 256.
// ---------------------------------------------------------------------------
#define AROWB 144                    // 72 bf16 per row
#define ATILE (64 * AROWB)           // 9216
#define AST (4 * ATILE)              // 36864 : KHI | KLO | VHI | VLO
#define ATTN_SM_BYTES (2 * AST)      // 73728

__device__ __forceinline__ void attn_load_stage(
    uint32_t sm, size_t key0, int tid)
{
    #pragma unroll
    for (int l = 0; l < 2; l++) {
        int idx = tid + l * 256;
        int r = idx >> 3, c = idx & 7;
        uint32_t dof = (uint32_t)(r * AROWB + c * 16);
        size_t   sof = ((size_t)r * DKH) * 2 + c * 16;
        cpasync16(sm + 0 * ATILE + dof, (const char*)(g_khi + key0) + sof);
        cpasync16(sm + 1 * ATILE + dof, (const char*)(g_klo + key0) + sof);
        cpasync16(sm + 2 * ATILE + dof, (const char*)(g_vhi + key0) + sof);
        cpasync16(sm + 3 * ATILE + dof, (const char*)(g_vlo + key0) + sof);
    }
}

__global__ __launch_bounds__(256, 1) void attn_mma_kernel()
{
    extern __shared__ char smem[];
    const uint32_t smem_base = smem_to_u32(smem);
    const int tid  = threadIdx.x;
    const int lane = tid & 31;
    const int w    = tid >> 5;          // warp 0..7 -> q rows w*32..w*32+31

    const int bh = blockIdx.y;
    const int q0 = blockIdx.x * 256;
    const size_t base = (size_t)bh * SS * DKH;

    const int lrow  = lane & 15;
    const int lhalf = lane >> 4;

    // ---- stage Q (256 x 64): hi -> stage0 region, lo -> stage1 region ----
    {
        const __nv_bfloat16* Qh = g_qhi + base + (size_t)q0 * DKH;
        const __nv_bfloat16* Ql = g_qlo + base + (size_t)q0 * DKH;
        #pragma unroll
        for (int l = 0; l < 8; l++) {
            int idx = tid + l * 256;
            int r = idx >> 3, c = idx & 7;
            uint32_t dof = (uint32_t)(r * AROWB + c * 16);
            size_t   sof = ((size_t)r * DKH) * 2 + c * 16;
            cpasync16(smem_base + dof,       (const char*)Qh + sof);
            cpasync16(smem_base + AST + dof, (const char*)Ql + sof);
        }
        CP_COMMIT();
        CP_WAIT0();
    }
    __syncthreads();

    uint32_t qhi[2][4][4], qlo[2][4][4];   // [am][ks][regs]
    #pragma unroll
    for (int am = 0; am < 2; am++) {
        const uint32_t qa = smem_base +
            (uint32_t)((w * 32 + am * 16 + lrow) * AROWB + lhalf * 16);
        #pragma unroll
        for (int ks = 0; ks < 4; ks++) {
            ldsm_x4(qa + ks * 32, qhi[am][ks]);
            ldsm_x4(qa + AST + ks * 32, qlo[am][ks]);
        }
    }
    __syncthreads();     // all warps done reading Q
    attn_load_stage(smem_base, base, tid);
    CP_COMMIT();
    attn_load_stage(smem_base + AST, base + (size_t)64 * DKH, tid);
    CP_COMMIT();

    float o[2][8][4] = {};
    float m[2][2], l[2][2];
    #pragma unroll
    for (int am = 0; am < 2; am++) {
        m[am][0] = -1e30f; m[am][1] = -1e30f;
        l[am][0] = 0.0f;   l[am][1] = 0.0f;
    }

    const uint32_t lane_off = (uint32_t)(lrow * AROWB + lhalf * 16);

    for (int ch = 0; ch < 32; ch++) {
        if (ch >= 30) { CP_WAIT0(); } else { CP_WAIT1(); }
        __syncthreads();
        const uint32_t st = smem_base + (uint32_t)(ch & 1) * AST;
        const uint32_t kb = st + lane_off;

        // ---- S = Q K^T : 32 x 64 per warp, 3-pass ----
        float s[2][8][4] = {};
        #pragma unroll
        for (int ks = 0; ks < 4; ks++) {
            const uint32_t koff = ks * 32;
            #pragma unroll
            for (int bn = 0; bn < 4; bn++) {
                uint32_t kh[4], kl[4];
                ldsm_x4(kb + 0 * ATILE + bn * 16 * AROWB + koff, kh);
                ldsm_x4(kb + 1 * ATILE + bn * 16 * AROWB + koff, kl);
                #pragma unroll
                for (int am = 0; am < 2; am++) {
                    mma_bf16(s[am][2*bn],   qhi[am][ks], kh[0], kh[2]);
                    mma_bf16(s[am][2*bn+1], qhi[am][ks], kh[1], kh[3]);
                    mma_bf16(s[am][2*bn],   qhi[am][ks], kl[0], kl[2]);
                    mma_bf16(s[am][2*bn+1], qhi[am][ks], kl[1], kl[3]);
                    mma_bf16(s[am][2*bn],   qlo[am][ks], kh[0], kh[2]);
                    mma_bf16(s[am][2*bn+1], qlo[am][ks], kh[1], kh[3]);
                }
            }
        }

        // ---- online softmax per am group ----
        #pragma unroll
        for (int am = 0; am < 2; am++) {
            float mxA = -1e30f, mxB = -1e30f;
            #pragma unroll
            for (int j = 0; j < 8; j++) {
                mxA = fmaxf(mxA, fmaxf(s[am][j][0], s[am][j][1]));
                mxB = fmaxf(mxB, fmaxf(s[am][j][2], s[am][j][3]));
            }
            #pragma unroll
            for (int msk = 1; msk < 4; msk <<= 1) {
                mxA = fmaxf(mxA, __shfl_xor_sync(0xffffffffu, mxA, msk));
                mxB = fmaxf(mxB, __shfl_xor_sync(0xffffffffu, mxB, msk));
            }
            const float mnA = fmaxf(m[am][0], mxA);
            const float mnB = fmaxf(m[am][1], mxB);
            const float fA = __expf(m[am][0] - mnA);
            const float fB = __expf(m[am][1] - mnB);
            m[am][0] = mnA; m[am][1] = mnB;
            float rsA = 0.0f, rsB = 0.0f;
            #pragma unroll
            for (int j = 0; j < 8; j++) {
                s[am][j][0] = __expf(s[am][j][0] - mnA); rsA += s[am][j][0];
                s[am][j][1] = __expf(s[am][j][1] - mnA); rsA += s[am][j][1];
                s[am][j][2] = __expf(s[am][j][2] - mnB); rsB += s[am][j][2];
                s[am][j][3] = __expf(s[am][j][3] - mnB); rsB += s[am][j][3];
            }
            #pragma unroll
            for (int msk = 1; msk < 4; msk <<= 1) {
                rsA += __shfl_xor_sync(0xffffffffu, rsA, msk);
                rsB += __shfl_xor_sync(0xffffffffu, rsB, msk);
            }
            l[am][0] = l[am][0] * fA + rsA;
            l[am][1] = l[am][1] * fB + rsB;
            #pragma unroll
            for (int j = 0; j < 8; j++) {
                o[am][j][0] *= fA; o[am][j][1] *= fA;
                o[am][j][2] *= fB; o[am][j][3] *= fB;
            }
        }

        // ---- O += P V ----
        #pragma unroll
        for (int j = 0; j < 4; j++) {
            uint32_t ph[2][4], pl[2][4];
            #pragma unroll
            for (int am = 0; am < 2; am++) {
                __nv_bfloat16 hb[8]; float lw[8];
                split2(s[am][2*j][0],   hb[0], lw[0]);
                split2(s[am][2*j][1],   hb[1], lw[1]);
                split2(s[am][2*j][2],   hb[2], lw[2]);
                split2(s[am][2*j][3],   hb[3], lw[3]);
                split2(s[am][2*j+1][0], hb[4], lw[4]);
                split2(s[am][2*j+1][1], hb[5], lw[5]);
                split2(s[am][2*j+1][2], hb[6], lw[6]);
                split2(s[am][2*j+1][3], hb[7], lw[7]);
                union { __nv_bfloat162 b2; uint32_t u; } t;
                t.b2 = __nv_bfloat162(hb[0], hb[1]); ph[am][0] = t.u;
                t.b2 = __nv_bfloat162(hb[2], hb[3]); ph[am][1] = t.u;
                t.b2 = __nv_bfloat162(hb[4], hb[5]); ph[am][2] = t.u;
                t.b2 = __nv_bfloat162(hb[6], hb[7]); ph[am][3] = t.u;
                pl[am][0] = pkbf(lw[0], lw[1]);
                pl[am][1] = pkbf(lw[2], lw[3]);
                pl[am][2] = pkbf(lw[4], lw[5]);
                pl[am][3] = pkbf(lw[6], lw[7]);
            }
            const uint32_t vrow = st + (uint32_t)((j * 16 + lrow) * AROWB + lhalf * 16);
            #pragma unroll
            for (int dvp = 0; dvp < 4; dvp++) {
                uint32_t vh[4], vl[4];
                ldsm_x4_t(vrow + 2 * ATILE + dvp * 32, vh);
                ldsm_x4_t(vrow + 3 * ATILE + dvp * 32, vl);
                #pragma unroll
                for (int am = 0; am < 2; am++) {
                    mma_bf16(o[am][2*dvp],   ph[am], vh[0], vh[1]);
                    mma_bf16(o[am][2*dvp+1], ph[am], vh[2], vh[3]);
                    mma_bf16(o[am][2*dvp],   ph[am], vl[0], vl[1]);
                    mma_bf16(o[am][2*dvp+1], ph[am], vl[2], vl[3]);
                    mma_bf16(o[am][2*dvp],   pl[am], vh[0], vh[1]);
                    mma_bf16(o[am][2*dvp+1], pl[am], vh[2], vh[3]);
                }
            }
        }
        __syncthreads();
        if (ch + 2 < 32) {
            attn_load_stage(smem_base + (uint32_t)(ch & 1) * AST,
                            base + (size_t)((ch + 2) * 64) * DKH, tid);
            CP_COMMIT();
        }
    }

    // ---- epilogue: normalize, split hi/lo, write ctx [token][1024] ----
    const int b_ = bh / HH;
    const int h_ = bh % HH;
    #pragma unroll
    for (int am = 0; am < 2; am++) {
        const float invA = 1.0f / l[am][0];
        const float invB = 1.0f / l[am][1];
        const int rA = q0 + w * 32 + am * 16 + (lane >> 2);
        const int tokenA = b_ * SS + rA;
        const int tokenB = tokenA + 8;
        #pragma unroll
        for (int jj = 0; jj < 8; jj++) {
            const int col = h_ * DKH + jj * 8 + (lane & 3) * 2;
            {
                float v0 = o[am][jj][0] * invA, v1 = o[am][jj][1] * invA;
                __nv_bfloat16 h0, h1; float l0, l1;
                split2(v0, h0, l0); split2(v1, h1, l1);
                size_t idx = (size_t)tokenA * DD + col;
                *(__nv_bfloat162*)&g_chi[idx] = __nv_bfloat162(h0, h1);
                *(__nv_bfloat162*)&g_clo[idx] =
                    __nv_bfloat162(__float2bfloat16(l0), __float2bfloat16(l1));
            }
            {
                float v0 = o[am][jj][2] * invB, v1 = o[am][jj][3] * invB;
                __nv_bfloat16 h0, h1; float l0, l1;
                split2(v0, h0, l0); split2(v1, h1, l1);
                size_t idx = (size_t)tokenB * DD + col;
                *(__nv_bfloat162*)&g_chi[idx] = __nv_bfloat162(h0, h1);
                *(__nv_bfloat162*)&g_clo[idx] =
                    __nv_bfloat162(__float2bfloat16(l0), __float2bfloat16(l1));
            }
        }
    }
}

// ---------------------------------------------------------------------------
extern "C" void kernel_launch(void* const* d_in, const int* in_sizes, int n_in,
                              void* d_out, int out_size)
{
    const float* X  = (const float*)d_in[0];
    const float* Wq = (const float*)d_in[1];
    const float* bq = (const float*)d_in[2];
    const float* Wk = (const float*)d_in[3];
    const float* bk = (const float*)d_in[4];
    const float* Wv = (const float*)d_in[5];
    const float* bv = (const float*)d_in[6];
    const float* Wo = (const float*)d_in[7];
    const float* bo = (const float*)d_in[8];
    float* out = (float*)d_out;

    cudaFuncSetAttribute(qkv_mma_kernel,
                         cudaFuncAttributeMaxDynamicSharedMemorySize, GSM_BYTES);
    cudaFuncSetAttribute(out_mma_kernel,
                         cudaFuncAttributeMaxDynamicSharedMemorySize, GSM_BYTES);
    cudaFuncSetAttribute(attn_mma_kernel,
                         cudaFuncAttributeMaxDynamicSharedMemorySize, ATTN_SM_BYTES);

    conv_x_kernel<<<2048, 256>>>((const float4*)X);
    conv_w_kernel<<<dim3(16, 16, 3), 256>>>(Wq, Wk, Wv);
    conv_wo_kernel<<<dim3(16, 16), 256>>>(Wo);
    qkv_mma_kernel<<<dim3(32, 8, 3), 256, GSM_BYTES>>>(bq, bk, bv);
    attn_mma_kernel<<<dim3(8, 32), 256, ATTN_SM_BYTES>>>();
    out_mma_kernel<<<dim3(32, 8), 256, GSM_BYTES>>>(bo, out);
}